// round 5
// baseline (speedup 1.0000x reference)
#include <cuda_runtime.h>
#include <cstdint>
#include <cstddef>

// Problem constants (fixed by the benchmark)
//  x: (16, 64, 64, 512)  -> 65536 tokens x 512 ch
//  w_qkv: (512, 1536), b_qkv: (1536)
//  rel_pos: (225, 16)
//  w_out: (512, 512), b_out: (512)
//  window 8x8, shift 4, 16 heads, head_dim 32

#define M_TOK   65536
#define KDIM    512
#define N_QKV   1536
#define N_OUT   512
#define NHEADS  16

// Scratch (allocation-free rule: __device__ globals)
static __device__ float g_qkv[(size_t)M_TOK * N_QKV];   // 384 MB
static __device__ float g_att[(size_t)M_TOK * N_OUT];   // 128 MB

__device__ __forceinline__ uint32_t f2tf32(float f) {
    uint32_t u;
    asm("cvt.rna.tf32.f32 %0, %1;" : "=r"(u) : "f"(f));
    return u;
}

__device__ __forceinline__ void mma_tf32(float* d, const uint32_t* a, const uint32_t* b) {
    asm volatile(
        "mma.sync.aligned.m16n8k8.row.col.f32.tf32.tf32.f32 "
        "{%0,%1,%2,%3}, {%4,%5,%6,%7}, {%8,%9}, {%0,%1,%2,%3};\n"
        : "+f"(d[0]), "+f"(d[1]), "+f"(d[2]), "+f"(d[3])
        : "r"(a[0]), "r"(a[1]), "r"(a[2]), "r"(a[3]),
          "r"(b[0]), "r"(b[1]));
}

// ---------------------------------------------------------------------------
// Dense GEMM: C[M,N] = A[M,K] * B[K,N] + bias[N]  (fp32 in/out, tf32 compute)
// BM=128, BN=128, BK=16, 256 threads, double-buffered smem, 1 sync per tile.
// Requires M%128==0, N%128==0, K%16==0 (true for all uses here).
// ---------------------------------------------------------------------------
__global__ __launch_bounds__(256)
void gemm_tf32_kernel(const float* __restrict__ A, const float* __restrict__ Bm,
                      const float* __restrict__ bias, float* __restrict__ C,
                      int M, int N, int K)
{
    __shared__ __align__(16) uint32_t As[2][16][132];  // [k][m] (transposed), pad 4
    __shared__ __align__(16) uint32_t Bs[2][16][132];  // [k][n], pad 4

    const int bm   = blockIdx.y * 128;
    const int bn   = blockIdx.x * 128;
    const int tid  = threadIdx.x;
    const int lane = tid & 31;
    const int warp = tid >> 5;
    const int g    = lane >> 2;   // 0..7
    const int tig  = lane & 3;    // 0..3
    const int wm   = (warp >> 2) * 64;   // 0 / 64
    const int wn   = (warp & 3) * 32;    // 0 / 32 / 64 / 96

    // A tile loader mapping: 128 rows x 16 k, 2 float4 per thread
    const int ar = tid >> 2;          // 0..63
    const int ac = (tid & 3) << 2;    // 0,4,8,12
    // B tile loader mapping: 16 rows x 128 n, 2 float4 per thread
    const int br = tid >> 5;          // 0..7
    const int bc = lane << 2;         // 0..124

    float acc[4][4][4];
    #pragma unroll
    for (int a = 0; a < 4; a++)
        #pragma unroll
        for (int b = 0; b < 4; b++)
            #pragma unroll
            for (int c = 0; c < 4; c++) acc[a][b][c] = 0.f;

    float4 av0, av1, bv0, bv1;

    // Prologue: tile 0 -> buf 0
    av0 = *(const float4*)(A + (size_t)(bm + ar) * K + ac);
    av1 = *(const float4*)(A + (size_t)(bm + 64 + ar) * K + ac);
    bv0 = *(const float4*)(Bm + (size_t)(br) * N + bn + bc);
    bv1 = *(const float4*)(Bm + (size_t)(8 + br) * N + bn + bc);
    {
        As[0][ac + 0][ar]      = f2tf32(av0.x);
        As[0][ac + 1][ar]      = f2tf32(av0.y);
        As[0][ac + 2][ar]      = f2tf32(av0.z);
        As[0][ac + 3][ar]      = f2tf32(av0.w);
        As[0][ac + 0][64 + ar] = f2tf32(av1.x);
        As[0][ac + 1][64 + ar] = f2tf32(av1.y);
        As[0][ac + 2][64 + ar] = f2tf32(av1.z);
        As[0][ac + 3][64 + ar] = f2tf32(av1.w);
        uint4 u0, u1;
        u0.x = f2tf32(bv0.x); u0.y = f2tf32(bv0.y); u0.z = f2tf32(bv0.z); u0.w = f2tf32(bv0.w);
        u1.x = f2tf32(bv1.x); u1.y = f2tf32(bv1.y); u1.z = f2tf32(bv1.z); u1.w = f2tf32(bv1.w);
        *(uint4*)&Bs[0][br][bc]     = u0;
        *(uint4*)&Bs[0][8 + br][bc] = u1;
    }
    __syncthreads();

    const int T = K >> 4;
    for (int t = 0; t < T; t++) {
        const int cur = t & 1;
        const bool more = (t + 1 < T);
        if (more) {
            const int k0 = (t + 1) << 4;
            av0 = *(const float4*)(A + (size_t)(bm + ar) * K + k0 + ac);
            av1 = *(const float4*)(A + (size_t)(bm + 64 + ar) * K + k0 + ac);
            bv0 = *(const float4*)(Bm + (size_t)(k0 + br) * N + bn + bc);
            bv1 = *(const float4*)(Bm + (size_t)(k0 + 8 + br) * N + bn + bc);
        }

        #pragma unroll
        for (int s = 0; s < 2; s++) {
            uint32_t afr[4][4], bfr[4][2];
            #pragma unroll
            for (int mt = 0; mt < 4; mt++) {
                const int m = wm + mt * 16;
                afr[mt][0] = As[cur][s * 8 + tig    ][m + g];
                afr[mt][1] = As[cur][s * 8 + tig    ][m + g + 8];
                afr[mt][2] = As[cur][s * 8 + tig + 4][m + g];
                afr[mt][3] = As[cur][s * 8 + tig + 4][m + g + 8];
            }
            #pragma unroll
            for (int nt = 0; nt < 4; nt++) {
                const int n = wn + nt * 8;
                bfr[nt][0] = Bs[cur][s * 8 + tig    ][n + g];
                bfr[nt][1] = Bs[cur][s * 8 + tig + 4][n + g];
            }
            #pragma unroll
            for (int mt = 0; mt < 4; mt++)
                #pragma unroll
                for (int nt = 0; nt < 4; nt++)
                    mma_tf32(acc[mt][nt], afr[mt], bfr[nt]);
        }

        if (more) {
            const int nb = (t + 1) & 1;
            As[nb][ac + 0][ar]      = f2tf32(av0.x);
            As[nb][ac + 1][ar]      = f2tf32(av0.y);
            As[nb][ac + 2][ar]      = f2tf32(av0.z);
            As[nb][ac + 3][ar]      = f2tf32(av0.w);
            As[nb][ac + 0][64 + ar] = f2tf32(av1.x);
            As[nb][ac + 1][64 + ar] = f2tf32(av1.y);
            As[nb][ac + 2][64 + ar] = f2tf32(av1.z);
            As[nb][ac + 3][64 + ar] = f2tf32(av1.w);
            uint4 u0, u1;
            u0.x = f2tf32(bv0.x); u0.y = f2tf32(bv0.y); u0.z = f2tf32(bv0.z); u0.w = f2tf32(bv0.w);
            u1.x = f2tf32(bv1.x); u1.y = f2tf32(bv1.y); u1.z = f2tf32(bv1.z); u1.w = f2tf32(bv1.w);
            *(uint4*)&Bs[nb][br][bc]     = u0;
            *(uint4*)&Bs[nb][8 + br][bc] = u1;
        }
        __syncthreads();
    }

    // Epilogue: bias + store
    #pragma unroll
    for (int mt = 0; mt < 4; mt++) {
        #pragma unroll
        for (int nt = 0; nt < 4; nt++) {
            const int row0 = bm + wm + mt * 16 + g;
            const int col0 = bn + wn + nt * 8 + tig * 2;
            const float b0 = __ldg(bias + col0);
            const float b1 = __ldg(bias + col0 + 1);
            float2 r0, r1;
            r0.x = acc[mt][nt][0] + b0; r0.y = acc[mt][nt][1] + b1;
            r1.x = acc[mt][nt][2] + b0; r1.y = acc[mt][nt][3] + b1;
            *(float2*)(C + (size_t)row0 * N + col0)       = r0;
            *(float2*)(C + (size_t)(row0 + 8) * N + col0) = r1;
        }
    }
}

// ---------------------------------------------------------------------------
// Windowed attention. Block = (head, window). 128 threads = 2 per query row.
// Shift + window partition + inverse shift fold into one pixel mapping:
//   pixel(h) = (wh*8 + ph + 4) & 63   (same for w)
// ---------------------------------------------------------------------------
__device__ __forceinline__ int pix_row(int win, int t) {
    const int b  = win >> 6;
    const int wi = win & 63;
    const int h  = (((wi >> 3) << 3) + (t >> 3) + 4) & 63;
    const int w  = (((wi & 7) << 3) + (t & 7) + 4) & 63;
    return (((b << 6) | h) << 6) | w;   // b*4096 + h*64 + w
}

__global__ __launch_bounds__(128)
void attn_kernel(const float* __restrict__ qkv, const float* __restrict__ rel_pos,
                 float* __restrict__ att)
{
    const int head = blockIdx.x;
    const int win  = blockIdx.y;
    const int tid  = threadIdx.x;

    __shared__ __align__(16) float ks[64][32];
    __shared__ __align__(16) float vs[64][32];
    __shared__ float rp[225];

    // rel-pos bias column for this head
    for (int i = tid; i < 225; i += 128) rp[i] = __ldg(rel_pos + i * NHEADS + head);

    // load K, V tiles (64 x 32 each)
    for (int idx = tid; idx < 64 * 8; idx += 128) {
        const int row = idx >> 3;
        const int c4  = (idx & 7) << 2;
        const size_t base = (size_t)pix_row(win, row) * N_QKV + head * 32 + c4;
        *(float4*)&ks[row][c4] = *(const float4*)(qkv + base + 512);
        *(float4*)&vs[row][c4] = *(const float4*)(qkv + base + 1024);
    }
    __syncthreads();

    const int i    = tid >> 1;     // query row 0..63
    const int half = tid & 1;      // key half

    // q row for this thread (from L2; 128B contiguous)
    float4 q4[8];
    {
        const float4* qp = (const float4*)(qkv + (size_t)pix_row(win, i) * N_QKV + head * 32);
        #pragma unroll
        for (int u = 0; u < 8; u++) q4[u] = __ldg(qp + u);
    }

    const float scale = 0.17677669529663687f;   // 1/sqrt(32)
    const int yi = i >> 3, xi = i & 7;

    float l[32];
    #pragma unroll
    for (int jj = 0; jj < 32; jj++) {
        const int j = (half << 5) + jj;
        const float4* kp = (const float4*)&ks[j][0];
        float acc = 0.f;
        #pragma unroll
        for (int u = 0; u < 8; u++) {
            const float4 kv = kp[u];
            acc += q4[u].x * kv.x + q4[u].y * kv.y + q4[u].z * kv.z + q4[u].w * kv.w;
        }
        const int yj = j >> 3, xj = j & 7;
        l[jj] = acc * scale + rp[(yi - yj + 7) * 15 + (xi - xj + 7)];
    }

    // softmax over 64 keys (2 cooperating threads)
    float m = l[0];
    #pragma unroll
    for (int jj = 1; jj < 32; jj++) m = fmaxf(m, l[jj]);
    m = fmaxf(m, __shfl_xor_sync(0xffffffffu, m, 1));
    float s = 0.f;
    #pragma unroll
    for (int jj = 0; jj < 32; jj++) { l[jj] = __expf(l[jj] - m); s += l[jj]; }
    s += __shfl_xor_sync(0xffffffffu, s, 1);
    const float inv = 1.0f / s;

    // O = P * V  (partial over this thread's 32 keys)
    float4 o[8];
    #pragma unroll
    for (int u = 0; u < 8; u++) { o[u].x = 0.f; o[u].y = 0.f; o[u].z = 0.f; o[u].w = 0.f; }
    #pragma unroll
    for (int jj = 0; jj < 32; jj++) {
        const float p = l[jj] * inv;
        const int j = (half << 5) + jj;
        const float4* vp = (const float4*)&vs[j][0];
        #pragma unroll
        for (int u = 0; u < 8; u++) {
            const float4 vv = vp[u];
            o[u].x += p * vv.x; o[u].y += p * vv.y;
            o[u].z += p * vv.z; o[u].w += p * vv.w;
        }
    }
    // combine halves
    #pragma unroll
    for (int u = 0; u < 8; u++) {
        o[u].x += __shfl_xor_sync(0xffffffffu, o[u].x, 1);
        o[u].y += __shfl_xor_sync(0xffffffffu, o[u].y, 1);
        o[u].z += __shfl_xor_sync(0xffffffffu, o[u].z, 1);
        o[u].w += __shfl_xor_sync(0xffffffffu, o[u].w, 1);
    }
    if (half == 0) {
        float4* op = (float4*)(att + (size_t)pix_row(win, i) * N_OUT + head * 32);
        #pragma unroll
        for (int u = 0; u < 8; u++) op[u] = o[u];
    }
}

// ---------------------------------------------------------------------------
extern "C" void kernel_launch(void* const* d_in, const int* in_sizes, int n_in,
                              void* d_out, int out_size)
{
    const float* x       = (const float*)d_in[0];
    const float* w_qkv   = (const float*)d_in[1];
    const float* b_qkv   = (const float*)d_in[2];
    const float* rel_pos = (const float*)d_in[3];
    const float* w_out   = (const float*)d_in[4];
    const float* b_out   = (const float*)d_in[5];
    float* out = (float*)d_out;

    float *qkv = nullptr, *att = nullptr;
    cudaGetSymbolAddress((void**)&qkv, g_qkv);
    cudaGetSymbolAddress((void**)&att, g_att);

    // 1) QKV projection (pure GEMM, pixel order)
    gemm_tf32_kernel<<<dim3(N_QKV / 128, M_TOK / 128), dim3(256)>>>(
        x, w_qkv, b_qkv, qkv, M_TOK, N_QKV, KDIM);

    // 2) Shifted-window attention (gather/scatter by pixel mapping)
    attn_kernel<<<dim3(NHEADS, 1024), dim3(128)>>>(qkv, rel_pos, att);

    // 3) Output projection (pure GEMM, writes final output directly)
    gemm_tf32_kernel<<<dim3(N_OUT / 128, M_TOK / 128), dim3(256)>>>(
        att, w_out, b_out, out, M_TOK, N_OUT, KDIM);
}

// round 7
// speedup vs baseline: 1.0883x; 1.0883x over previous
#include <cuda_runtime.h>
#include <cstdint>
#include <cstddef>

// Problem constants (fixed by the benchmark)
//  x: (16, 64, 64, 512)  -> 65536 tokens x 512 ch
//  w_qkv: (512, 1536), b_qkv: (1536)
//  rel_pos: (225, 16)
//  w_out: (512, 512), b_out: (512)
//  window 8x8, shift 4, 16 heads, head_dim 32

#define M_TOK   65536
#define KDIM    512
#define N_QKV   1536
#define N_OUT   512
#define NHEADS  16

// Scratch (allocation-free rule: __device__ globals)
static __device__ float g_qkv[(size_t)M_TOK * N_QKV];   // 384 MB
static __device__ float g_att[(size_t)M_TOK * N_OUT];   // 128 MB
static __device__ float g_btq[(size_t)N_QKV * KDIM];    // 3 MB  (w_qkv^T, K-major)
static __device__ float g_bto[(size_t)N_OUT * KDIM];    // 1 MB  (w_out^T, K-major)

__device__ __forceinline__ uint32_t f2tf32(float f) {
    uint32_t u;
    asm("cvt.rna.tf32.f32 %0, %1;" : "=r"(u) : "f"(f));
    return u;
}

__device__ __forceinline__ void mma_tf32(float* d, const uint32_t* a, const uint32_t* b) {
    asm volatile(
        "mma.sync.aligned.m16n8k8.row.col.f32.tf32.tf32.f32 "
        "{%0,%1,%2,%3}, {%4,%5,%6,%7}, {%8,%9}, {%0,%1,%2,%3};\n"
        : "+f"(d[0]), "+f"(d[1]), "+f"(d[2]), "+f"(d[3])
        : "r"(a[0]), "r"(a[1]), "r"(a[2]), "r"(a[3]),
          "r"(b[0]), "r"(b[1]));
}

// ---------------------------------------------------------------------------
// Weight transpose: out[c][r] = in[r][c].  R, C multiples of 32.
// ---------------------------------------------------------------------------
__global__ void transpose_kernel(const float* __restrict__ in, float* __restrict__ out,
                                 int R, int C) {
    __shared__ float t[32][33];
    const int c0 = blockIdx.x * 32, r0 = blockIdx.y * 32;
    const int x = threadIdx.x, y = threadIdx.y;
    #pragma unroll
    for (int dy = 0; dy < 32; dy += 8)
        t[y + dy][x] = in[(size_t)(r0 + y + dy) * C + c0 + x];
    __syncthreads();
    #pragma unroll
    for (int dy = 0; dy < 32; dy += 8)
        out[(size_t)(c0 + y + dy) * R + r0 + x] = t[x][y + dy];
}

// ---------------------------------------------------------------------------
// Dense GEMM: C[M,N] = A[M,K]*B[K,N] + bias[N], Bt = B^T (N rows, K cols).
// fp32 in/out, tf32 mma.sync compute. BM=128, BN=128, BK=16, 256 threads,
// double-buffered smem with XOR-swizzled 16B-chunk layout:
//   word(row, k) = row*16 + ((k>>2) ^ ((row>>1)&3))*4 + (k&3)
// -> STS.128 staging and scalar fragment LDS are both provably bank-conflict
//    free. Requires K % 16 == 0 (K = 512 here).
// ---------------------------------------------------------------------------
__global__ __launch_bounds__(256, 2)
void gemm_tf32_kernel(const float* __restrict__ A, const float* __restrict__ Bt,
                      const float* __restrict__ bias, float* __restrict__ C,
                      int N, int K)
{
    __shared__ __align__(16) uint32_t sA[2][2048];   // 128 rows x 16 k
    __shared__ __align__(16) uint32_t sB[2][2048];   // 128 n-rows x 16 k

    const int bm   = blockIdx.y * 128;
    const int bn   = blockIdx.x * 128;
    const int tid  = threadIdx.x;
    const int lane = tid & 31;
    const int warp = tid >> 5;
    const int g    = lane >> 2;   // 0..7
    const int tig  = lane & 3;    // 0..3
    const int wm   = (warp >> 2) * 64;   // 0 / 64
    const int wn   = (warp & 3) * 32;    // 0 / 32 / 64 / 96

    // loader mapping: rows r and r+64, one 16B chunk each
    const int lr = tid >> 2;          // 0..63
    const int lc = tid & 3;           // chunk 0..3
    const uint32_t so1 = (uint32_t)(lr * 16        + ((lc ^ ((lr >> 1) & 3)) << 2));
    const uint32_t so2 = (uint32_t)((lr + 64) * 16 + ((lc ^ ((lr >> 1) & 3)) << 2));
    const float* Ap1 = A  + (size_t)(bm + lr) * K + lc * 4;
    const float* Ap2 = A  + (size_t)(bm + lr + 64) * K + lc * 4;
    const float* Bp1 = Bt + (size_t)(bn + lr) * K + lc * 4;
    const float* Bp2 = Bt + (size_t)(bn + lr + 64) * K + lc * 4;

    // per-warp fragment bases (row*16) and xor keys
    uint32_t abase[4], bbase[4];
    uint32_t akey[4], bkey[4];
    #pragma unroll
    for (int mt = 0; mt < 4; mt++) {
        const int m0 = wm + mt * 16 + g;
        abase[mt] = (uint32_t)(m0 * 16) + tig;
        akey[mt]  = (uint32_t)((m0 >> 1) & 3);
    }
    #pragma unroll
    for (int nt = 0; nt < 4; nt++) {
        const int n0 = wn + nt * 8 + g;
        bbase[nt] = (uint32_t)(n0 * 16) + tig;
        bkey[nt]  = (uint32_t)((n0 >> 1) & 3);
    }

    float acc[4][4][4];
    #pragma unroll
    for (int a = 0; a < 4; a++)
        #pragma unroll
        for (int b = 0; b < 4; b++)
            #pragma unroll
            for (int c = 0; c < 4; c++) acc[a][b][c] = 0.f;

    float4 av0, av1, bv0, bv1;

    // prologue: tile 0 -> buf 0
    av0 = __ldg((const float4*)Ap1);
    av1 = __ldg((const float4*)Ap2);
    bv0 = __ldg((const float4*)Bp1);
    bv1 = __ldg((const float4*)Bp2);
    {
        uint4 w;
        w.x = f2tf32(av0.x); w.y = f2tf32(av0.y); w.z = f2tf32(av0.z); w.w = f2tf32(av0.w);
        *(uint4*)&sA[0][so1] = w;
        w.x = f2tf32(av1.x); w.y = f2tf32(av1.y); w.z = f2tf32(av1.z); w.w = f2tf32(av1.w);
        *(uint4*)&sA[0][so2] = w;
        w.x = f2tf32(bv0.x); w.y = f2tf32(bv0.y); w.z = f2tf32(bv0.z); w.w = f2tf32(bv0.w);
        *(uint4*)&sB[0][so1] = w;
        w.x = f2tf32(bv1.x); w.y = f2tf32(bv1.y); w.z = f2tf32(bv1.z); w.w = f2tf32(bv1.w);
        *(uint4*)&sB[0][so2] = w;
    }
    __syncthreads();

    const int T = K >> 4;
    for (int t = 0; t < T; t++) {
        const int cur = t & 1;
        const bool more = (t + 1 < T);
        if (more) {
            const int k0 = (t + 1) << 4;
            av0 = __ldg((const float4*)(Ap1 + k0));
            av1 = __ldg((const float4*)(Ap2 + k0));
            bv0 = __ldg((const float4*)(Bp1 + k0));
            bv1 = __ldg((const float4*)(Bp2 + k0));
        }

        #pragma unroll
        for (int s = 0; s < 2; s++) {
            uint32_t afr[4][4], bfr[4][2];
            const uint32_t c0 = (uint32_t)(2 * s);
            const uint32_t c1 = c0 + 1;
            #pragma unroll
            for (int mt = 0; mt < 4; mt++) {
                const uint32_t o0 = abase[mt] + ((c0 ^ akey[mt]) << 2);
                const uint32_t o1 = abase[mt] + ((c1 ^ akey[mt]) << 2);
                afr[mt][0] = sA[cur][o0];
                afr[mt][1] = sA[cur][o0 + 128];   // +8 rows (same key)
                afr[mt][2] = sA[cur][o1];
                afr[mt][3] = sA[cur][o1 + 128];
            }
            #pragma unroll
            for (int nt = 0; nt < 4; nt++) {
                bfr[nt][0] = sB[cur][bbase[nt] + ((c0 ^ bkey[nt]) << 2)];
                bfr[nt][1] = sB[cur][bbase[nt] + ((c1 ^ bkey[nt]) << 2)];
            }
            #pragma unroll
            for (int mt = 0; mt < 4; mt++)
                #pragma unroll
                for (int nt = 0; nt < 4; nt++)
                    mma_tf32(acc[mt][nt], afr[mt], bfr[nt]);
        }

        if (more) {
            const int nb = (t + 1) & 1;
            uint4 w;
            w.x = f2tf32(av0.x); w.y = f2tf32(av0.y); w.z = f2tf32(av0.z); w.w = f2tf32(av0.w);
            *(uint4*)&sA[nb][so1] = w;
            w.x = f2tf32(av1.x); w.y = f2tf32(av1.y); w.z = f2tf32(av1.z); w.w = f2tf32(av1.w);
            *(uint4*)&sA[nb][so2] = w;
            w.x = f2tf32(bv0.x); w.y = f2tf32(bv0.y); w.z = f2tf32(bv0.z); w.w = f2tf32(bv0.w);
            *(uint4*)&sB[nb][so1] = w;
            w.x = f2tf32(bv1.x); w.y = f2tf32(bv1.y); w.z = f2tf32(bv1.z); w.w = f2tf32(bv1.w);
            *(uint4*)&sB[nb][so2] = w;
        }
        __syncthreads();
    }

    // Epilogue: bias + store
    #pragma unroll
    for (int mt = 0; mt < 4; mt++) {
        #pragma unroll
        for (int nt = 0; nt < 4; nt++) {
            const int row0 = bm + wm + mt * 16 + g;
            const int col0 = bn + wn + nt * 8 + tig * 2;
            const float b0 = __ldg(bias + col0);
            const float b1 = __ldg(bias + col0 + 1);
            float2 r0, r1;
            r0.x = acc[mt][nt][0] + b0; r0.y = acc[mt][nt][1] + b1;
            r1.x = acc[mt][nt][2] + b0; r1.y = acc[mt][nt][3] + b1;
            *(float2*)(C + (size_t)row0 * N + col0)       = r0;
            *(float2*)(C + (size_t)(row0 + 8) * N + col0) = r1;
        }
    }
}

// ---------------------------------------------------------------------------
// Windowed attention. Block = (head, window). 128 threads = 2 per query row.
// Shift + window partition + inverse shift fold into one pixel mapping:
//   pixel(h) = (wh*8 + ph + 4) & 63   (same for w)
// ---------------------------------------------------------------------------
__device__ __forceinline__ int pix_row(int win, int t) {
    const int b  = win >> 6;
    const int wi = win & 63;
    const int h  = (((wi >> 3) << 3) + (t >> 3) + 4) & 63;
    const int w  = (((wi & 7) << 3) + (t & 7) + 4) & 63;
    return (((b << 6) | h) << 6) | w;   // b*4096 + h*64 + w
}

__global__ __launch_bounds__(128)
void attn_kernel(const float* __restrict__ qkv, const float* __restrict__ rel_pos,
                 float* __restrict__ att)
{
    const int head = blockIdx.x;
    const int win  = blockIdx.y;
    const int tid  = threadIdx.x;

    __shared__ __align__(16) float ks[64][32];
    __shared__ __align__(16) float vs[64][32];
    __shared__ float rp[225];

    for (int i = tid; i < 225; i += 128) rp[i] = __ldg(rel_pos + i * NHEADS + head);

    for (int idx = tid; idx < 64 * 8; idx += 128) {
        const int row = idx >> 3;
        const int c4  = (idx & 7) << 2;
        const size_t base = (size_t)pix_row(win, row) * N_QKV + head * 32 + c4;
        *(float4*)&ks[row][c4] = *(const float4*)(qkv + base + 512);
        *(float4*)&vs[row][c4] = *(const float4*)(qkv + base + 1024);
    }
    __syncthreads();

    const int i    = tid >> 1;
    const int half = tid & 1;

    float4 q4[8];
    {
        const float4* qp = (const float4*)(qkv + (size_t)pix_row(win, i) * N_QKV + head * 32);
        #pragma unroll
        for (int u = 0; u < 8; u++) q4[u] = __ldg(qp + u);
    }

    const float scale = 0.17677669529663687f;   // 1/sqrt(32)
    const int yi = i >> 3, xi = i & 7;

    float l[32];
    #pragma unroll
    for (int jj = 0; jj < 32; jj++) {
        const int j = (half << 5) + jj;
        const float4* kp = (const float4*)&ks[j][0];
        float acc = 0.f;
        #pragma unroll
        for (int u = 0; u < 8; u++) {
            const float4 kv = kp[u];
            acc += q4[u].x * kv.x + q4[u].y * kv.y + q4[u].z * kv.z + q4[u].w * kv.w;
        }
        const int yj = j >> 3, xj = j & 7;
        l[jj] = acc * scale + rp[(yi - yj + 7) * 15 + (xi - xj + 7)];
    }

    float m = l[0];
    #pragma unroll
    for (int jj = 1; jj < 32; jj++) m = fmaxf(m, l[jj]);
    m = fmaxf(m, __shfl_xor_sync(0xffffffffu, m, 1));
    float s = 0.f;
    #pragma unroll
    for (int jj = 0; jj < 32; jj++) { l[jj] = __expf(l[jj] - m); s += l[jj]; }
    s += __shfl_xor_sync(0xffffffffu, s, 1);
    const float inv = 1.0f / s;

    float4 o[8];
    #pragma unroll
    for (int u = 0; u < 8; u++) { o[u].x = 0.f; o[u].y = 0.f; o[u].z = 0.f; o[u].w = 0.f; }
    #pragma unroll
    for (int jj = 0; jj < 32; jj++) {
        const float p = l[jj] * inv;
        const int j = (half << 5) + jj;
        const float4* vp = (const float4*)&vs[j][0];
        #pragma unroll
        for (int u = 0; u < 8; u++) {
            const float4 vv = vp[u];
            o[u].x += p * vv.x; o[u].y += p * vv.y;
            o[u].z += p * vv.z; o[u].w += p * vv.w;
        }
    }
    #pragma unroll
    for (int u = 0; u < 8; u++) {
        o[u].x += __shfl_xor_sync(0xffffffffu, o[u].x, 1);
        o[u].y += __shfl_xor_sync(0xffffffffu, o[u].y, 1);
        o[u].z += __shfl_xor_sync(0xffffffffu, o[u].z, 1);
        o[u].w += __shfl_xor_sync(0xffffffffu, o[u].w, 1);
    }
    if (half == 0) {
        float4* op = (float4*)(att + (size_t)pix_row(win, i) * N_OUT + head * 32);
        #pragma unroll
        for (int u = 0; u < 8; u++) op[u] = o[u];
    }
}

// ---------------------------------------------------------------------------
extern "C" void kernel_launch(void* const* d_in, const int* in_sizes, int n_in,
                              void* d_out, int out_size)
{
    const float* x       = (const float*)d_in[0];
    const float* w_qkv   = (const float*)d_in[1];
    const float* b_qkv   = (const float*)d_in[2];
    const float* rel_pos = (const float*)d_in[3];
    const float* w_out   = (const float*)d_in[4];
    const float* b_out   = (const float*)d_in[5];
    float* out = (float*)d_out;

    float *qkv = nullptr, *att = nullptr, *btq = nullptr, *bto = nullptr;
    cudaGetSymbolAddress((void**)&qkv, g_qkv);
    cudaGetSymbolAddress((void**)&att, g_att);
    cudaGetSymbolAddress((void**)&btq, g_btq);
    cudaGetSymbolAddress((void**)&bto, g_bto);

    // 0) transpose weights to K-major (tiny, once per launch)
    transpose_kernel<<<dim3(N_QKV / 32, KDIM / 32), dim3(32, 8)>>>(w_qkv, btq, KDIM, N_QKV);
    transpose_kernel<<<dim3(N_OUT / 32, KDIM / 32), dim3(32, 8)>>>(w_out, bto, KDIM, N_OUT);

    // 1) QKV projection
    gemm_tf32_kernel<<<dim3(N_QKV / 128, M_TOK / 128), 256>>>(
        x, btq, b_qkv, qkv, N_QKV, KDIM);

    // 2) Shifted-window attention
    attn_kernel<<<dim3(NHEADS, 1024), dim3(128)>>>(qkv, rel_pos, att);

    // 3) Output projection (writes final output)
    gemm_tf32_kernel<<<dim3(N_OUT / 128, M_TOK / 128), 256>>>(
        att, bto, b_out, out, N_OUT, KDIM);
}

// round 8
// speedup vs baseline: 1.4125x; 1.2979x over previous
#include <cuda_runtime.h>
#include <cstdint>
#include <cstddef>

// Problem constants (fixed by the benchmark)
//  x: (16, 64, 64, 512)  -> 65536 tokens x 512 ch
//  w_qkv: (512, 1536), b_qkv: (1536)
//  rel_pos: (225, 16)
//  w_out: (512, 512), b_out: (512)
//  window 8x8, shift 4, 16 heads, head_dim 32

#define M_TOK   65536
#define KDIM    512
#define N_QKV   1536
#define N_OUT   512
#define NHEADS  16

// Scratch (allocation-free rule: __device__ globals)
static __device__ float g_qkv[(size_t)M_TOK * N_QKV];   // 384 MB
static __device__ float g_att[(size_t)M_TOK * N_OUT];   // 128 MB
static __device__ float g_btq[(size_t)N_QKV * KDIM];    // 3 MB  (w_qkv^T, K-major)
static __device__ float g_bto[(size_t)N_OUT * KDIM];    // 1 MB  (w_out^T, K-major)

__device__ __forceinline__ uint32_t f2tf32(float f) {
    uint32_t u;
    asm("cvt.rna.tf32.f32 %0, %1;" : "=r"(u) : "f"(f));
    return u;
}

__device__ __forceinline__ void mma_tf32(float* d, const uint32_t* a, const uint32_t* b) {
    asm volatile(
        "mma.sync.aligned.m16n8k8.row.col.f32.tf32.tf32.f32 "
        "{%0,%1,%2,%3}, {%4,%5,%6,%7}, {%8,%9}, {%0,%1,%2,%3};\n"
        : "+f"(d[0]), "+f"(d[1]), "+f"(d[2]), "+f"(d[3])
        : "r"(a[0]), "r"(a[1]), "r"(a[2]), "r"(a[3]),
          "r"(b[0]), "r"(b[1]));
}

// ---------------------------------------------------------------------------
// Weight transpose: out[c][r] = in[r][c].  R, C multiples of 32.
// ---------------------------------------------------------------------------
__global__ void transpose_kernel(const float* __restrict__ in, float* __restrict__ out,
                                 int R, int C) {
    __shared__ float t[32][33];
    const int c0 = blockIdx.x * 32, r0 = blockIdx.y * 32;
    const int x = threadIdx.x, y = threadIdx.y;
    #pragma unroll
    for (int dy = 0; dy < 32; dy += 8)
        t[y + dy][x] = in[(size_t)(r0 + y + dy) * C + c0 + x];
    __syncthreads();
    #pragma unroll
    for (int dy = 0; dy < 32; dy += 8)
        out[(size_t)(c0 + y + dy) * R + r0 + x] = t[x][y + dy];
}

// ---------------------------------------------------------------------------
// Dense GEMM: C[M,N] = A[M,K]*B[K,N] + bias[N], Bt = B^T (N rows, K cols).
// fp32 in/out, tf32 mma.sync compute. BM=128, BN=128, BK=16, 256 threads,
// double-buffered smem with XOR-swizzled 16B-chunk layout.
// ---------------------------------------------------------------------------
__global__ __launch_bounds__(256, 2)
void gemm_tf32_kernel(const float* __restrict__ A, const float* __restrict__ Bt,
                      const float* __restrict__ bias, float* __restrict__ C,
                      int N, int K)
{
    __shared__ __align__(16) uint32_t sA[2][2048];   // 128 rows x 16 k
    __shared__ __align__(16) uint32_t sB[2][2048];   // 128 n-rows x 16 k

    const int bm   = blockIdx.y * 128;
    const int bn   = blockIdx.x * 128;
    const int tid  = threadIdx.x;
    const int lane = tid & 31;
    const int warp = tid >> 5;
    const int g    = lane >> 2;
    const int tig  = lane & 3;
    const int wm   = (warp >> 2) * 64;
    const int wn   = (warp & 3) * 32;

    const int lr = tid >> 2;
    const int lc = tid & 3;
    const uint32_t so1 = (uint32_t)(lr * 16        + ((lc ^ ((lr >> 1) & 3)) << 2));
    const uint32_t so2 = (uint32_t)((lr + 64) * 16 + ((lc ^ ((lr >> 1) & 3)) << 2));
    const float* Ap1 = A  + (size_t)(bm + lr) * K + lc * 4;
    const float* Ap2 = A  + (size_t)(bm + lr + 64) * K + lc * 4;
    const float* Bp1 = Bt + (size_t)(bn + lr) * K + lc * 4;
    const float* Bp2 = Bt + (size_t)(bn + lr + 64) * K + lc * 4;

    uint32_t abase[4], bbase[4];
    uint32_t akey[4], bkey[4];
    #pragma unroll
    for (int mt = 0; mt < 4; mt++) {
        const int m0 = wm + mt * 16 + g;
        abase[mt] = (uint32_t)(m0 * 16) + tig;
        akey[mt]  = (uint32_t)((m0 >> 1) & 3);
    }
    #pragma unroll
    for (int nt = 0; nt < 4; nt++) {
        const int n0 = wn + nt * 8 + g;
        bbase[nt] = (uint32_t)(n0 * 16) + tig;
        bkey[nt]  = (uint32_t)((n0 >> 1) & 3);
    }

    float acc[4][4][4];
    #pragma unroll
    for (int a = 0; a < 4; a++)
        #pragma unroll
        for (int b = 0; b < 4; b++)
            #pragma unroll
            for (int c = 0; c < 4; c++) acc[a][b][c] = 0.f;

    float4 av0, av1, bv0, bv1;

    av0 = __ldg((const float4*)Ap1);
    av1 = __ldg((const float4*)Ap2);
    bv0 = __ldg((const float4*)Bp1);
    bv1 = __ldg((const float4*)Bp2);
    {
        uint4 w;
        w.x = f2tf32(av0.x); w.y = f2tf32(av0.y); w.z = f2tf32(av0.z); w.w = f2tf32(av0.w);
        *(uint4*)&sA[0][so1] = w;
        w.x = f2tf32(av1.x); w.y = f2tf32(av1.y); w.z = f2tf32(av1.z); w.w = f2tf32(av1.w);
        *(uint4*)&sA[0][so2] = w;
        w.x = f2tf32(bv0.x); w.y = f2tf32(bv0.y); w.z = f2tf32(bv0.z); w.w = f2tf32(bv0.w);
        *(uint4*)&sB[0][so1] = w;
        w.x = f2tf32(bv1.x); w.y = f2tf32(bv1.y); w.z = f2tf32(bv1.z); w.w = f2tf32(bv1.w);
        *(uint4*)&sB[0][so2] = w;
    }
    __syncthreads();

    const int T = K >> 4;
    for (int t = 0; t < T; t++) {
        const int cur = t & 1;
        const bool more = (t + 1 < T);
        if (more) {
            const int k0 = (t + 1) << 4;
            av0 = __ldg((const float4*)(Ap1 + k0));
            av1 = __ldg((const float4*)(Ap2 + k0));
            bv0 = __ldg((const float4*)(Bp1 + k0));
            bv1 = __ldg((const float4*)(Bp2 + k0));
        }

        #pragma unroll
        for (int s = 0; s < 2; s++) {
            uint32_t afr[4][4], bfr[4][2];
            const uint32_t c0 = (uint32_t)(2 * s);
            const uint32_t c1 = c0 + 1;
            #pragma unroll
            for (int mt = 0; mt < 4; mt++) {
                const uint32_t o0 = abase[mt] + ((c0 ^ akey[mt]) << 2);
                const uint32_t o1 = abase[mt] + ((c1 ^ akey[mt]) << 2);
                afr[mt][0] = sA[cur][o0];
                afr[mt][1] = sA[cur][o0 + 128];
                afr[mt][2] = sA[cur][o1];
                afr[mt][3] = sA[cur][o1 + 128];
            }
            #pragma unroll
            for (int nt = 0; nt < 4; nt++) {
                bfr[nt][0] = sB[cur][bbase[nt] + ((c0 ^ bkey[nt]) << 2)];
                bfr[nt][1] = sB[cur][bbase[nt] + ((c1 ^ bkey[nt]) << 2)];
            }
            #pragma unroll
            for (int mt = 0; mt < 4; mt++)
                #pragma unroll
                for (int nt = 0; nt < 4; nt++)
                    mma_tf32(acc[mt][nt], afr[mt], bfr[nt]);
        }

        if (more) {
            const int nb = (t + 1) & 1;
            uint4 w;
            w.x = f2tf32(av0.x); w.y = f2tf32(av0.y); w.z = f2tf32(av0.z); w.w = f2tf32(av0.w);
            *(uint4*)&sA[nb][so1] = w;
            w.x = f2tf32(av1.x); w.y = f2tf32(av1.y); w.z = f2tf32(av1.z); w.w = f2tf32(av1.w);
            *(uint4*)&sA[nb][so2] = w;
            w.x = f2tf32(bv0.x); w.y = f2tf32(bv0.y); w.z = f2tf32(bv0.z); w.w = f2tf32(bv0.w);
            *(uint4*)&sB[nb][so1] = w;
            w.x = f2tf32(bv1.x); w.y = f2tf32(bv1.y); w.z = f2tf32(bv1.z); w.w = f2tf32(bv1.w);
            *(uint4*)&sB[nb][so2] = w;
        }
        __syncthreads();
    }

    #pragma unroll
    for (int mt = 0; mt < 4; mt++) {
        #pragma unroll
        for (int nt = 0; nt < 4; nt++) {
            const int row0 = bm + wm + mt * 16 + g;
            const int col0 = bn + wn + nt * 8 + tig * 2;
            const float b0 = __ldg(bias + col0);
            const float b1 = __ldg(bias + col0 + 1);
            float2 r0, r1;
            r0.x = acc[mt][nt][0] + b0; r0.y = acc[mt][nt][1] + b1;
            r1.x = acc[mt][nt][2] + b0; r1.y = acc[mt][nt][3] + b1;
            *(float2*)(C + (size_t)row0 * N + col0)       = r0;
            *(float2*)(C + (size_t)(row0 + 8) * N + col0) = r1;
        }
    }
}

// ---------------------------------------------------------------------------
// Windowed attention via mma.sync tf32.
// Block = (head, window), 128 threads = 4 warps, warp w owns query rows
// [16w, 16w+16). S = Q*K^T (m64n64k32), softmax in accumulator layout,
// O = P*V (m64n32k64) with P staged through smem (overlaying Q/K).
// Shift + window partition + inverse shift fold into one pixel mapping:
//   pixel(h) = (wh*8 + ph + 4) & 63   (same for w)
// ---------------------------------------------------------------------------
__device__ __forceinline__ int pix_row(int win, int t) {
    const int b  = win >> 6;
    const int wi = win & 63;
    const int h  = (((wi >> 3) << 3) + (t >> 3) + 4) & 63;
    const int w  = (((wi & 7) << 3) + (t & 7) + 4) & 63;
    return (((b << 6) | h) << 6) | w;   // b*4096 + h*64 + w
}

// swizzled smem offsets (word indices), 16B-chunk XOR swizzle
__device__ __forceinline__ int qoff(int row, int dim) {   // 32-float rows
    return row * 32 + (((dim >> 2) ^ (row & 7)) << 2) + (dim & 3);
}
__device__ __forceinline__ int poff(int row, int col) {   // 64-float rows
    return row * 64 + (((col >> 2) ^ (row & 7)) << 2) + (col & 3);
}

__global__ __launch_bounds__(128)
void attn_mma_kernel(const float* __restrict__ qkv, const float* __restrict__ rel_pos,
                     float* __restrict__ att)
{
    const int head = blockIdx.x;
    const int win  = blockIdx.y;
    const int tid  = threadIdx.x;
    const int lane = tid & 31;
    const int g    = lane >> 2;
    const int tig  = lane & 3;
    const int m0   = (tid >> 5) * 16;    // warp's query-row base

    __shared__ __align__(16) uint32_t sQK[4096];  // Q[0..2047], K[2048..4095]; reused as P[64][64]
    __shared__ __align__(16) uint32_t vst[2048];  // V^T: [dim][key], swizzled
    __shared__ float rp[225];

    // ---- stage ----
    for (int i = tid; i < 225; i += 128) rp[i] = __ldg(rel_pos + i * NHEADS + head);
    {
        const int row  = tid >> 1;
        const int half = tid & 1;
        const size_t base = (size_t)pix_row(win, row) * N_QKV + head * 32 + half * 16;
        const float4* qp = (const float4*)(qkv + base);
        const float4* kp = (const float4*)(qkv + base + 512);
        const float4* vp = (const float4*)(qkv + base + 1024);
        const float scale = 0.17677669529663687f;   // 1/sqrt(32)
        #pragma unroll
        for (int u = 0; u < 4; u++) {
            const int d0 = half * 16 + u * 4;
            float4 v4 = __ldg(qp + u);
            uint4 w;
            w.x = f2tf32(v4.x * scale); w.y = f2tf32(v4.y * scale);
            w.z = f2tf32(v4.z * scale); w.w = f2tf32(v4.w * scale);
            *(uint4*)&sQK[qoff(row, d0)] = w;
            v4 = __ldg(kp + u);
            w.x = f2tf32(v4.x); w.y = f2tf32(v4.y); w.z = f2tf32(v4.z); w.w = f2tf32(v4.w);
            *(uint4*)&sQK[2048 + qoff(row, d0)] = w;
            v4 = __ldg(vp + u);
            vst[poff(d0 + 0, row)] = f2tf32(v4.x);
            vst[poff(d0 + 1, row)] = f2tf32(v4.y);
            vst[poff(d0 + 2, row)] = f2tf32(v4.z);
            vst[poff(d0 + 3, row)] = f2tf32(v4.w);
        }
    }
    __syncthreads();

    // ---- S = Q*K^T  (m16n64k32 per warp) ----
    float acc[8][4];
    #pragma unroll
    for (int nt = 0; nt < 8; nt++)
        #pragma unroll
        for (int c = 0; c < 4; c++) acc[nt][c] = 0.f;

    #pragma unroll
    for (int kt = 0; kt < 4; kt++) {
        uint32_t a[4];
        a[0] = sQK[qoff(m0 + g,     kt * 8 + tig)];
        a[1] = sQK[qoff(m0 + g + 8, kt * 8 + tig)];
        a[2] = sQK[qoff(m0 + g,     kt * 8 + tig + 4)];
        a[3] = sQK[qoff(m0 + g + 8, kt * 8 + tig + 4)];
        #pragma unroll
        for (int nt = 0; nt < 8; nt++) {
            uint32_t b[2];
            b[0] = sQK[2048 + qoff(nt * 8 + g, kt * 8 + tig)];
            b[1] = sQK[2048 + qoff(nt * 8 + g, kt * 8 + tig + 4)];
            mma_tf32(acc[nt], a, b);
        }
    }

    // ---- bias + softmax (rows i0 = m0+g and i0+8) ----
    const int i0 = m0 + g;
    const int yi = i0 >> 3, xi = i0 & 7;
    float mx0 = -1e30f, mx1 = -1e30f;
    #pragma unroll
    for (int nt = 0; nt < 8; nt++) {
        const int bi = (yi - nt + 7) * 15 + (xi - 2 * tig + 7);
        acc[nt][0] += rp[bi];
        acc[nt][1] += rp[bi - 1];
        acc[nt][2] += rp[bi + 15];
        acc[nt][3] += rp[bi + 14];
        mx0 = fmaxf(mx0, fmaxf(acc[nt][0], acc[nt][1]));
        mx1 = fmaxf(mx1, fmaxf(acc[nt][2], acc[nt][3]));
    }
    mx0 = fmaxf(mx0, __shfl_xor_sync(0xffffffffu, mx0, 1));
    mx0 = fmaxf(mx0, __shfl_xor_sync(0xffffffffu, mx0, 2));
    mx1 = fmaxf(mx1, __shfl_xor_sync(0xffffffffu, mx1, 1));
    mx1 = fmaxf(mx1, __shfl_xor_sync(0xffffffffu, mx1, 2));

    float s0 = 0.f, s1 = 0.f;
    #pragma unroll
    for (int nt = 0; nt < 8; nt++) {
        acc[nt][0] = __expf(acc[nt][0] - mx0);
        acc[nt][1] = __expf(acc[nt][1] - mx0);
        acc[nt][2] = __expf(acc[nt][2] - mx1);
        acc[nt][3] = __expf(acc[nt][3] - mx1);
        s0 += acc[nt][0] + acc[nt][1];
        s1 += acc[nt][2] + acc[nt][3];
    }
    s0 += __shfl_xor_sync(0xffffffffu, s0, 1);
    s0 += __shfl_xor_sync(0xffffffffu, s0, 2);
    s1 += __shfl_xor_sync(0xffffffffu, s1, 1);
    s1 += __shfl_xor_sync(0xffffffffu, s1, 2);
    const float inv0 = 1.0f / s0;
    const float inv1 = 1.0f / s1;

    // ---- stage P (overlays Q/K region; all warps done reading Q/K first) ----
    __syncthreads();
    #pragma unroll
    for (int nt = 0; nt < 8; nt++) {
        const int o0 = poff(i0,     nt * 8 + 2 * tig);
        const int o1 = poff(i0 + 8, nt * 8 + 2 * tig);
        sQK[o0]     = f2tf32(acc[nt][0] * inv0);
        sQK[o0 + 1] = f2tf32(acc[nt][1] * inv0);
        sQK[o1]     = f2tf32(acc[nt][2] * inv1);
        sQK[o1 + 1] = f2tf32(acc[nt][3] * inv1);
    }
    __syncwarp();   // each warp reads only its own 16 P rows

    // ---- O = P*V  (m16n32k64 per warp) ----
    float accO[4][4];
    #pragma unroll
    for (int nt = 0; nt < 4; nt++)
        #pragma unroll
        for (int c = 0; c < 4; c++) accO[nt][c] = 0.f;

    #pragma unroll
    for (int kt = 0; kt < 8; kt++) {
        uint32_t a[4];
        a[0] = sQK[poff(m0 + g,     kt * 8 + tig)];
        a[1] = sQK[poff(m0 + g + 8, kt * 8 + tig)];
        a[2] = sQK[poff(m0 + g,     kt * 8 + tig + 4)];
        a[3] = sQK[poff(m0 + g + 8, kt * 8 + tig + 4)];
        #pragma unroll
        for (int nt = 0; nt < 4; nt++) {
            uint32_t b[2];
            b[0] = vst[poff(nt * 8 + g, kt * 8 + tig)];
            b[1] = vst[poff(nt * 8 + g, kt * 8 + tig + 4)];
            mma_tf32(accO[nt], a, b);
        }
    }

    // ---- epilogue ----
    {
        const size_t r0 = (size_t)pix_row(win, i0)     * N_OUT + head * 32;
        const size_t r1 = (size_t)pix_row(win, i0 + 8) * N_OUT + head * 32;
        #pragma unroll
        for (int nt = 0; nt < 4; nt++) {
            float2 w0, w1;
            w0.x = accO[nt][0]; w0.y = accO[nt][1];
            w1.x = accO[nt][2]; w1.y = accO[nt][3];
            *(float2*)(att + r0 + nt * 8 + 2 * tig) = w0;
            *(float2*)(att + r1 + nt * 8 + 2 * tig) = w1;
        }
    }
}

// ---------------------------------------------------------------------------
extern "C" void kernel_launch(void* const* d_in, const int* in_sizes, int n_in,
                              void* d_out, int out_size)
{
    const float* x       = (const float*)d_in[0];
    const float* w_qkv   = (const float*)d_in[1];
    const float* b_qkv   = (const float*)d_in[2];
    const float* rel_pos = (const float*)d_in[3];
    const float* w_out   = (const float*)d_in[4];
    const float* b_out   = (const float*)d_in[5];
    float* out = (float*)d_out;

    float *qkv = nullptr, *att = nullptr, *btq = nullptr, *bto = nullptr;
    cudaGetSymbolAddress((void**)&qkv, g_qkv);
    cudaGetSymbolAddress((void**)&att, g_att);
    cudaGetSymbolAddress((void**)&btq, g_btq);
    cudaGetSymbolAddress((void**)&bto, g_bto);

    // 0) transpose weights to K-major (tiny, once per launch)
    transpose_kernel<<<dim3(N_QKV / 32, KDIM / 32), dim3(32, 8)>>>(w_qkv, btq, KDIM, N_QKV);
    transpose_kernel<<<dim3(N_OUT / 32, KDIM / 32), dim3(32, 8)>>>(w_out, bto, KDIM, N_OUT);

    // 1) QKV projection
    gemm_tf32_kernel<<<dim3(N_QKV / 128, M_TOK / 128), 256>>>(
        x, btq, b_qkv, qkv, N_QKV, KDIM);

    // 2) Shifted-window attention (tensor-core)
    attn_mma_kernel<<<dim3(NHEADS, 1024), dim3(128)>>>(qkv, rel_pos, att);

    // 3) Output projection (writes final output)
    gemm_tf32_kernel<<<dim3(N_OUT / 128, M_TOK / 128), 256>>>(
        att, bto, b_out, out, N_OUT, KDIM);
}

// round 9
// speedup vs baseline: 1.7322x; 1.2263x over previous
#include <cuda_runtime.h>
#include <cstdint>
#include <cstddef>

// Problem constants (fixed by the benchmark)
//  x: (16, 64, 64, 512)  -> 65536 tokens x 512 ch
//  w_qkv: (512, 1536), b_qkv: (1536)
//  rel_pos: (225, 16)
//  w_out: (512, 512), b_out: (512)
//  window 8x8, shift 4, 16 heads, head_dim 32

#define M_TOK   65536
#define KDIM    512
#define N_QKV   1536
#define N_OUT   512
#define NHEADS  16

// Scratch (allocation-free rule: __device__ globals)
static __device__ float g_qkv[(size_t)M_TOK * N_QKV];   // 384 MB
static __device__ float g_att[(size_t)M_TOK * N_OUT];   // 128 MB
static __device__ float g_btq[(size_t)N_QKV * KDIM];    // 3 MB  (w_qkv^T, K-major)
static __device__ float g_bto[(size_t)N_OUT * KDIM];    // 1 MB  (w_out^T, K-major)

__device__ __forceinline__ uint32_t f2tf32(float f) {
    uint32_t u;
    asm("cvt.rna.tf32.f32 %0, %1;" : "=r"(u) : "f"(f));
    return u;
}

__device__ __forceinline__ uint32_t smem_u32(const void* p) {
    uint32_t a;
    asm("{ .reg .u64 t; cvta.to.shared.u64 t, %1; cvt.u32.u64 %0, t; }" : "=r"(a) : "l"(p));
    return a;
}

__device__ __forceinline__ void mma_tf32(float* d, const uint32_t* a, const uint32_t* b) {
    asm volatile(
        "mma.sync.aligned.m16n8k8.row.col.f32.tf32.tf32.f32 "
        "{%0,%1,%2,%3}, {%4,%5,%6,%7}, {%8,%9}, {%0,%1,%2,%3};\n"
        : "+f"(d[0]), "+f"(d[1]), "+f"(d[2]), "+f"(d[3])
        : "r"(a[0]), "r"(a[1]), "r"(a[2]), "r"(a[3]),
          "r"(b[0]), "r"(b[1]));
}

// ldmatrix x4: four 8x8 b16 tiles == four 8x4 tf32 tiles.
// Thread t receives, from tile (t>>3): tf32 element (row t/4 & 7..., col t%4).
__device__ __forceinline__ void ldsm_x4(uint32_t* r, uint32_t saddr) {
    asm volatile("ldmatrix.sync.aligned.m8n8.x4.shared.b16 {%0,%1,%2,%3}, [%4];"
                 : "=r"(r[0]), "=r"(r[1]), "=r"(r[2]), "=r"(r[3]) : "r"(saddr));
}

// ---------------------------------------------------------------------------
// Weight transpose: out[c][r] = in[r][c].  R, C multiples of 32.
// ---------------------------------------------------------------------------
__global__ void transpose_kernel(const float* __restrict__ in, float* __restrict__ out,
                                 int R, int C) {
    __shared__ float t[32][33];
    const int c0 = blockIdx.x * 32, r0 = blockIdx.y * 32;
    const int x = threadIdx.x, y = threadIdx.y;
    #pragma unroll
    for (int dy = 0; dy < 32; dy += 8)
        t[y + dy][x] = in[(size_t)(r0 + y + dy) * C + c0 + x];
    __syncthreads();
    #pragma unroll
    for (int dy = 0; dy < 32; dy += 8)
        out[(size_t)(c0 + y + dy) * R + r0 + x] = t[x][y + dy];
}

// ---------------------------------------------------------------------------
// Dense GEMM: C[M,N] = A[M,K]*B[K,N] + bias[N], Bt = B^T (N rows, K cols).
// fp32 in/out, tf32 mma.sync compute. BM=128, BN=128, BK=16, 256 threads,
// double-buffered smem with XOR-swizzled 16B-chunk layout:
//   word(row, k) = row*16 + ((k>>2) ^ ((row>>1)&3))*4 + (k&3)
// Operand fragments via ldmatrix.x4 (tf32-as-b16 trick): 6 LDSM / 16 MMA.
// ---------------------------------------------------------------------------
__global__ __launch_bounds__(256, 2)
void gemm_tf32_kernel(const float* __restrict__ A, const float* __restrict__ Bt,
                      const float* __restrict__ bias, float* __restrict__ C,
                      int N, int K)
{
    __shared__ __align__(16) uint32_t sA[2][2048];   // 128 rows x 16 k
    __shared__ __align__(16) uint32_t sB[2][2048];   // 128 n-rows x 16 k

    const int bm   = blockIdx.y * 128;
    const int bn   = blockIdx.x * 128;
    const int tid  = threadIdx.x;
    const int lane = tid & 31;
    const int warp = tid >> 5;
    const int g    = lane >> 2;
    const int tig  = lane & 3;
    const int wm   = (warp >> 2) * 64;
    const int wn   = (warp & 3) * 32;

    const int lr = tid >> 2;
    const int lc = tid & 3;
    const uint32_t so1 = (uint32_t)(lr * 16        + ((lc ^ ((lr >> 1) & 3)) << 2));
    const uint32_t so2 = (uint32_t)((lr + 64) * 16 + ((lc ^ ((lr >> 1) & 3)) << 2));
    const float* Ap1 = A  + (size_t)(bm + lr) * K + lc * 4;
    const float* Ap2 = A  + (size_t)(bm + lr + 64) * K + lc * 4;
    const float* Bp1 = Bt + (size_t)(bn + lr) * K + lc * 4;
    const float* Bp2 = Bt + (size_t)(bn + lr + 64) * K + lc * 4;

    // ldmatrix per-thread addresses (byte offsets into a buffer), s=0 chunks.
    // A x4 tiles: (rows lo, c0), (rows hi, c0), (lo, c0+1), (hi, c0+1)
    //   -> row +8 on lane bit3, chunk +1 on lane bit4.
    // B x4 tiles: (n lo, c0), (lo, c0+1), (hi, c0), (hi, c0+1)
    //   -> chunk +1 on lane bit3, row +8 on lane bit4.
    const uint32_t aBase0 = smem_u32(&sA[0][0]);
    const uint32_t aBase1 = smem_u32(&sA[1][0]);
    const uint32_t bBase0 = smem_u32(&sB[0][0]);
    const uint32_t bBase1 = smem_u32(&sB[1][0]);
    const int r8 = lane & 7;
    uint32_t aoff[4], boff[2];
    #pragma unroll
    for (int mt = 0; mt < 4; mt++) {
        const int m = wm + mt * 16 + r8 + ((lane >> 3) & 1) * 8;
        const int c = lane >> 4;
        aoff[mt] = (uint32_t)(m * 64 + ((c ^ ((m >> 1) & 3)) << 4));
    }
    #pragma unroll
    for (int np = 0; np < 2; np++) {
        const int n = wn + np * 16 + r8 + (lane >> 4) * 8;
        const int c = (lane >> 3) & 1;
        boff[np] = (uint32_t)(n * 64 + ((c ^ ((n >> 1) & 3)) << 4));
    }

    float acc[4][4][4];
    #pragma unroll
    for (int a = 0; a < 4; a++)
        #pragma unroll
        for (int b = 0; b < 4; b++)
            #pragma unroll
            for (int c = 0; c < 4; c++) acc[a][b][c] = 0.f;

    float4 av0, av1, bv0, bv1;

    av0 = __ldg((const float4*)Ap1);
    av1 = __ldg((const float4*)Ap2);
    bv0 = __ldg((const float4*)Bp1);
    bv1 = __ldg((const float4*)Bp2);
    {
        uint4 w;
        w.x = f2tf32(av0.x); w.y = f2tf32(av0.y); w.z = f2tf32(av0.z); w.w = f2tf32(av0.w);
        *(uint4*)&sA[0][so1] = w;
        w.x = f2tf32(av1.x); w.y = f2tf32(av1.y); w.z = f2tf32(av1.z); w.w = f2tf32(av1.w);
        *(uint4*)&sA[0][so2] = w;
        w.x = f2tf32(bv0.x); w.y = f2tf32(bv0.y); w.z = f2tf32(bv0.z); w.w = f2tf32(bv0.w);
        *(uint4*)&sB[0][so1] = w;
        w.x = f2tf32(bv1.x); w.y = f2tf32(bv1.y); w.z = f2tf32(bv1.z); w.w = f2tf32(bv1.w);
        *(uint4*)&sB[0][so2] = w;
    }
    __syncthreads();

    const int T = K >> 4;
    for (int t = 0; t < T; t++) {
        const int cur = t & 1;
        const uint32_t aB = cur ? aBase1 : aBase0;
        const uint32_t bB = cur ? bBase1 : bBase0;
        const bool more = (t + 1 < T);
        if (more) {
            const int k0 = (t + 1) << 4;
            av0 = __ldg((const float4*)(Ap1 + k0));
            av1 = __ldg((const float4*)(Ap2 + k0));
            bv0 = __ldg((const float4*)(Bp1 + k0));
            bv1 = __ldg((const float4*)(Bp2 + k0));
        }

        #pragma unroll
        for (int s = 0; s < 2; s++) {
            const uint32_t sx = (uint32_t)(s << 5);   // chunk+2 == XOR 32 bytes
            uint32_t afr[4][4], bfr[2][4];
            #pragma unroll
            for (int mt = 0; mt < 4; mt++)
                ldsm_x4(afr[mt], aB + (aoff[mt] ^ sx));
            #pragma unroll
            for (int np = 0; np < 2; np++)
                ldsm_x4(bfr[np], bB + (boff[np] ^ sx));
            #pragma unroll
            for (int mt = 0; mt < 4; mt++)
                #pragma unroll
                for (int nt = 0; nt < 4; nt++)
                    mma_tf32(acc[mt][nt], afr[mt], &bfr[nt >> 1][(nt & 1) * 2]);
        }

        if (more) {
            const int nb = (t + 1) & 1;
            uint4 w;
            w.x = f2tf32(av0.x); w.y = f2tf32(av0.y); w.z = f2tf32(av0.z); w.w = f2tf32(av0.w);
            *(uint4*)&sA[nb][so1] = w;
            w.x = f2tf32(av1.x); w.y = f2tf32(av1.y); w.z = f2tf32(av1.z); w.w = f2tf32(av1.w);
            *(uint4*)&sA[nb][so2] = w;
            w.x = f2tf32(bv0.x); w.y = f2tf32(bv0.y); w.z = f2tf32(bv0.z); w.w = f2tf32(bv0.w);
            *(uint4*)&sB[nb][so1] = w;
            w.x = f2tf32(bv1.x); w.y = f2tf32(bv1.y); w.z = f2tf32(bv1.z); w.w = f2tf32(bv1.w);
            *(uint4*)&sB[nb][so2] = w;
        }
        __syncthreads();
    }

    #pragma unroll
    for (int mt = 0; mt < 4; mt++) {
        #pragma unroll
        for (int nt = 0; nt < 4; nt++) {
            const int row0 = bm + wm + mt * 16 + g;
            const int col0 = bn + wn + nt * 8 + tig * 2;
            const float b0 = __ldg(bias + col0);
            const float b1 = __ldg(bias + col0 + 1);
            float2 r0, r1;
            r0.x = acc[mt][nt][0] + b0; r0.y = acc[mt][nt][1] + b1;
            r1.x = acc[mt][nt][2] + b0; r1.y = acc[mt][nt][3] + b1;
            *(float2*)(C + (size_t)row0 * N + col0)       = r0;
            *(float2*)(C + (size_t)(row0 + 8) * N + col0) = r1;
        }
    }
}

// ---------------------------------------------------------------------------
// Windowed attention via mma.sync tf32.
// Block = (head, window), 128 threads = 4 warps, warp w owns query rows
// [16w, 16w+16). S = Q*K^T (m64n64k32), softmax in accumulator layout,
// O = P*V (m64n32k64) with P staged through smem (overlaying Q/K).
// Shift + window partition + inverse shift fold into one pixel mapping:
//   pixel(h) = (wh*8 + ph + 4) & 63   (same for w)
// ---------------------------------------------------------------------------
__device__ __forceinline__ int pix_row(int win, int t) {
    const int b  = win >> 6;
    const int wi = win & 63;
    const int h  = (((wi >> 3) << 3) + (t >> 3) + 4) & 63;
    const int w  = (((wi & 7) << 3) + (t & 7) + 4) & 63;
    return (((b << 6) | h) << 6) | w;   // b*4096 + h*64 + w
}

// swizzled smem offsets (word indices), 16B-chunk XOR swizzle
__device__ __forceinline__ int qoff(int row, int dim) {   // 32-float rows
    return row * 32 + (((dim >> 2) ^ (row & 7)) << 2) + (dim & 3);
}
__device__ __forceinline__ int poff(int row, int col) {   // 64-float rows
    return row * 64 + (((col >> 2) ^ (row & 7)) << 2) + (col & 3);
}

__global__ __launch_bounds__(128)
void attn_mma_kernel(const float* __restrict__ qkv, const float* __restrict__ rel_pos,
                     float* __restrict__ att)
{
    const int head = blockIdx.x;
    const int win  = blockIdx.y;
    const int tid  = threadIdx.x;
    const int lane = tid & 31;
    const int g    = lane >> 2;
    const int tig  = lane & 3;
    const int m0   = (tid >> 5) * 16;    // warp's query-row base

    __shared__ __align__(16) uint32_t sQK[4096];  // Q[0..2047], K[2048..4095]; reused as P[64][64]
    __shared__ __align__(16) uint32_t vst[2048];  // V^T: [dim][key], swizzled
    __shared__ float rp[225];

    // ---- stage ----
    for (int i = tid; i < 225; i += 128) rp[i] = __ldg(rel_pos + i * NHEADS + head);
    {
        const int row  = tid >> 1;
        const int half = tid & 1;
        const size_t base = (size_t)pix_row(win, row) * N_QKV + head * 32 + half * 16;
        const float4* qp = (const float4*)(qkv + base);
        const float4* kp = (const float4*)(qkv + base + 512);
        const float4* vp = (const float4*)(qkv + base + 1024);
        const float scale = 0.17677669529663687f;   // 1/sqrt(32)
        #pragma unroll
        for (int u = 0; u < 4; u++) {
            const int d0 = half * 16 + u * 4;
            float4 v4 = __ldg(qp + u);
            uint4 w;
            w.x = f2tf32(v4.x * scale); w.y = f2tf32(v4.y * scale);
            w.z = f2tf32(v4.z * scale); w.w = f2tf32(v4.w * scale);
            *(uint4*)&sQK[qoff(row, d0)] = w;
            v4 = __ldg(kp + u);
            w.x = f2tf32(v4.x); w.y = f2tf32(v4.y); w.z = f2tf32(v4.z); w.w = f2tf32(v4.w);
            *(uint4*)&sQK[2048 + qoff(row, d0)] = w;
            v4 = __ldg(vp + u);
            vst[poff(d0 + 0, row)] = f2tf32(v4.x);
            vst[poff(d0 + 1, row)] = f2tf32(v4.y);
            vst[poff(d0 + 2, row)] = f2tf32(v4.z);
            vst[poff(d0 + 3, row)] = f2tf32(v4.w);
        }
    }
    __syncthreads();

    // ---- S = Q*K^T  (m16n64k32 per warp) ----
    float acc[8][4];
    #pragma unroll
    for (int nt = 0; nt < 8; nt++)
        #pragma unroll
        for (int c = 0; c < 4; c++) acc[nt][c] = 0.f;

    #pragma unroll
    for (int kt = 0; kt < 4; kt++) {
        uint32_t a[4];
        a[0] = sQK[qoff(m0 + g,     kt * 8 + tig)];
        a[1] = sQK[qoff(m0 + g + 8, kt * 8 + tig)];
        a[2] = sQK[qoff(m0 + g,     kt * 8 + tig + 4)];
        a[3] = sQK[qoff(m0 + g + 8, kt * 8 + tig + 4)];
        #pragma unroll
        for (int nt = 0; nt < 8; nt++) {
            uint32_t b[2];
            b[0] = sQK[2048 + qoff(nt * 8 + g, kt * 8 + tig)];
            b[1] = sQK[2048 + qoff(nt * 8 + g, kt * 8 + tig + 4)];
            mma_tf32(acc[nt], a, b);
        }
    }

    // ---- bias + softmax (rows i0 = m0+g and i0+8) ----
    const int i0 = m0 + g;
    const int yi = i0 >> 3, xi = i0 & 7;
    float mx0 = -1e30f, mx1 = -1e30f;
    #pragma unroll
    for (int nt = 0; nt < 8; nt++) {
        const int bi = (yi - nt + 7) * 15 + (xi - 2 * tig + 7);
        acc[nt][0] += rp[bi];
        acc[nt][1] += rp[bi - 1];
        acc[nt][2] += rp[bi + 15];
        acc[nt][3] += rp[bi + 14];
        mx0 = fmaxf(mx0, fmaxf(acc[nt][0], acc[nt][1]));
        mx1 = fmaxf(mx1, fmaxf(acc[nt][2], acc[nt][3]));
    }
    mx0 = fmaxf(mx0, __shfl_xor_sync(0xffffffffu, mx0, 1));
    mx0 = fmaxf(mx0, __shfl_xor_sync(0xffffffffu, mx0, 2));
    mx1 = fmaxf(mx1, __shfl_xor_sync(0xffffffffu, mx1, 1));
    mx1 = fmaxf(mx1, __shfl_xor_sync(0xffffffffu, mx1, 2));

    float s0 = 0.f, s1 = 0.f;
    #pragma unroll
    for (int nt = 0; nt < 8; nt++) {
        acc[nt][0] = __expf(acc[nt][0] - mx0);
        acc[nt][1] = __expf(acc[nt][1] - mx0);
        acc[nt][2] = __expf(acc[nt][2] - mx1);
        acc[nt][3] = __expf(acc[nt][3] - mx1);
        s0 += acc[nt][0] + acc[nt][1];
        s1 += acc[nt][2] + acc[nt][3];
    }
    s0 += __shfl_xor_sync(0xffffffffu, s0, 1);
    s0 += __shfl_xor_sync(0xffffffffu, s0, 2);
    s1 += __shfl_xor_sync(0xffffffffu, s1, 1);
    s1 += __shfl_xor_sync(0xffffffffu, s1, 2);
    const float inv0 = 1.0f / s0;
    const float inv1 = 1.0f / s1;

    // ---- stage P (overlays Q/K region; all warps done reading Q/K first) ----
    __syncthreads();
    #pragma unroll
    for (int nt = 0; nt < 8; nt++) {
        const int o0 = poff(i0,     nt * 8 + 2 * tig);
        const int o1 = poff(i0 + 8, nt * 8 + 2 * tig);
        sQK[o0]     = f2tf32(acc[nt][0] * inv0);
        sQK[o0 + 1] = f2tf32(acc[nt][1] * inv0);
        sQK[o1]     = f2tf32(acc[nt][2] * inv1);
        sQK[o1 + 1] = f2tf32(acc[nt][3] * inv1);
    }
    __syncwarp();   // each warp reads only its own 16 P rows

    // ---- O = P*V  (m16n32k64 per warp) ----
    float accO[4][4];
    #pragma unroll
    for (int nt = 0; nt < 4; nt++)
        #pragma unroll
        for (int c = 0; c < 4; c++) accO[nt][c] = 0.f;

    #pragma unroll
    for (int kt = 0; kt < 8; kt++) {
        uint32_t a[4];
        a[0] = sQK[poff(m0 + g,     kt * 8 + tig)];
        a[1] = sQK[poff(m0 + g + 8, kt * 8 + tig)];
        a[2] = sQK[poff(m0 + g,     kt * 8 + tig + 4)];
        a[3] = sQK[poff(m0 + g + 8, kt * 8 + tig + 4)];
        #pragma unroll
        for (int nt = 0; nt < 4; nt++) {
            uint32_t b[2];
            b[0] = vst[poff(nt * 8 + g, kt * 8 + tig)];
            b[1] = vst[poff(nt * 8 + g, kt * 8 + tig + 4)];
            mma_tf32(accO[nt], a, b);
        }
    }

    // ---- epilogue ----
    {
        const size_t r0 = (size_t)pix_row(win, i0)     * N_OUT + head * 32;
        const size_t r1 = (size_t)pix_row(win, i0 + 8) * N_OUT + head * 32;
        #pragma unroll
        for (int nt = 0; nt < 4; nt++) {
            float2 w0, w1;
            w0.x = accO[nt][0]; w0.y = accO[nt][1];
            w1.x = accO[nt][2]; w1.y = accO[nt][3];
            *(float2*)(att + r0 + nt * 8 + 2 * tig) = w0;
            *(float2*)(att + r1 + nt * 8 + 2 * tig) = w1;
        }
    }
}

// ---------------------------------------------------------------------------
extern "C" void kernel_launch(void* const* d_in, const int* in_sizes, int n_in,
                              void* d_out, int out_size)
{
    const float* x       = (const float*)d_in[0];
    const float* w_qkv   = (const float*)d_in[1];
    const float* b_qkv   = (const float*)d_in[2];
    const float* rel_pos = (const float*)d_in[3];
    const float* w_out   = (const float*)d_in[4];
    const float* b_out   = (const float*)d_in[5];
    float* out = (float*)d_out;

    float *qkv = nullptr, *att = nullptr, *btq = nullptr, *bto = nullptr;
    cudaGetSymbolAddress((void**)&qkv, g_qkv);
    cudaGetSymbolAddress((void**)&att, g_att);
    cudaGetSymbolAddress((void**)&btq, g_btq);
    cudaGetSymbolAddress((void**)&bto, g_bto);

    // 0) transpose weights to K-major (tiny, once per launch)
    transpose_kernel<<<dim3(N_QKV / 32, KDIM / 32), dim3(32, 8)>>>(w_qkv, btq, KDIM, N_QKV);
    transpose_kernel<<<dim3(N_OUT / 32, KDIM / 32), dim3(32, 8)>>>(w_out, bto, KDIM, N_OUT);

    // 1) QKV projection
    gemm_tf32_kernel<<<dim3(N_QKV / 128, M_TOK / 128), 256>>>(
        x, btq, b_qkv, qkv, N_QKV, KDIM);

    // 2) Shifted-window attention (tensor-core)
    attn_mma_kernel<<<dim3(NHEADS, 1024), dim3(128)>>>(qkv, rel_pos, att);

    // 3) Output projection (writes final output)
    gemm_tf32_kernel<<<dim3(N_OUT / 128, M_TOK / 128), 256>>>(
        att, bto, b_out, out, N_OUT, KDIM);
}

// round 11
// speedup vs baseline: 2.0182x; 1.1651x over previous
#include <cuda_runtime.h>
#include <cuda_fp16.h>
#include <cstdint>
#include <cstddef>

// Problem constants (fixed by the benchmark)
//  x: (16, 64, 64, 512)  -> 65536 tokens x 512 ch
//  w_qkv: (512, 1536), b_qkv: (1536)
//  rel_pos: (225, 16)
//  w_out: (512, 512), b_out: (512)
//  window 8x8, shift 4, 16 heads, head_dim 32

#define M_TOK   65536
#define KDIM    512
#define N_QKV   1536
#define N_OUT   512
#define NHEADS  16

// Scratch (allocation-free rule: __device__ globals)
static __device__ float g_qkv[(size_t)M_TOK * N_QKV];   // 384 MB
static __device__ float g_att[(size_t)M_TOK * N_OUT];   // 128 MB
static __device__ float g_btq[(size_t)N_QKV * KDIM];    // 3 MB  (w_qkv^T, K-major)
static __device__ float g_bto[(size_t)N_OUT * KDIM];    // 1 MB  (w_out^T, K-major)

__device__ __forceinline__ uint32_t f2tf32(float f) {
    uint32_t u;
    asm("cvt.rna.tf32.f32 %0, %1;" : "=r"(u) : "f"(f));
    return u;
}

// pack two floats into f16x2 (lo in low 16 bits)
__device__ __forceinline__ uint32_t pack_h2(float lo, float hi) {
    uint32_t r;
    asm("cvt.rn.f16x2.f32 %0, %1, %2;" : "=r"(r) : "f"(hi), "f"(lo));
    return r;
}

__device__ __forceinline__ uint32_t smem_u32(const void* p) {
    uint32_t a;
    asm("{ .reg .u64 t; cvta.to.shared.u64 t, %1; cvt.u32.u64 %0, t; }" : "=r"(a) : "l"(p));
    return a;
}

__device__ __forceinline__ void mma_tf32(float* d, const uint32_t* a, const uint32_t* b) {
    asm volatile(
        "mma.sync.aligned.m16n8k8.row.col.f32.tf32.tf32.f32 "
        "{%0,%1,%2,%3}, {%4,%5,%6,%7}, {%8,%9}, {%0,%1,%2,%3};\n"
        : "+f"(d[0]), "+f"(d[1]), "+f"(d[2]), "+f"(d[3])
        : "r"(a[0]), "r"(a[1]), "r"(a[2]), "r"(a[3]),
          "r"(b[0]), "r"(b[1]));
}

__device__ __forceinline__ void mma_f16(float* d, const uint32_t* a, const uint32_t* b) {
    asm volatile(
        "mma.sync.aligned.m16n8k16.row.col.f32.f16.f16.f32 "
        "{%0,%1,%2,%3}, {%4,%5,%6,%7}, {%8,%9}, {%0,%1,%2,%3};\n"
        : "+f"(d[0]), "+f"(d[1]), "+f"(d[2]), "+f"(d[3])
        : "r"(a[0]), "r"(a[1]), "r"(a[2]), "r"(a[3]),
          "r"(b[0]), "r"(b[1]));
}

__device__ __forceinline__ void ldsm_x4(uint32_t* r, uint32_t saddr) {
    asm volatile("ldmatrix.sync.aligned.m8n8.x4.shared.b16 {%0,%1,%2,%3}, [%4];"
                 : "=r"(r[0]), "=r"(r[1]), "=r"(r[2]), "=r"(r[3]) : "r"(saddr));
}

// ---------------------------------------------------------------------------
// Weight transpose: out[c][r] = in[r][c].  R, C multiples of 32.
// ---------------------------------------------------------------------------
__global__ void transpose_kernel(const float* __restrict__ in, float* __restrict__ out,
                                 int R, int C) {
    __shared__ float t[32][33];
    const int c0 = blockIdx.x * 32, r0 = blockIdx.y * 32;
    const int x = threadIdx.x, y = threadIdx.y;
    #pragma unroll
    for (int dy = 0; dy < 32; dy += 8)
        t[y + dy][x] = in[(size_t)(r0 + y + dy) * C + c0 + x];
    __syncthreads();
    #pragma unroll
    for (int dy = 0; dy < 32; dy += 8)
        out[(size_t)(c0 + y + dy) * R + r0 + x] = t[x][y + dy];
}

// ---------------------------------------------------------------------------
// Dense GEMM: C[M,N] = A[M,K]*B[K,N] + bias[N], Bt = B^T (N rows, K cols).
// fp32 in/out, fp16 mma.sync (m16n8k16, fp32 accum). BM=128, BN=128, BK=32,
// 256 threads, double-buffered smem.
// Smem tile: 128 rows x 32 fp16 = 64 B/row = 4 x 16B chunks, XOR swizzle
//   chunk' = chunk ^ ((row>>1)&3)  -> STS.128 and all ldmatrix phases
//   are bank-conflict-free (verified by enumeration).
// ---------------------------------------------------------------------------
__global__ __launch_bounds__(256, 2)
void gemm_f16_kernel(const float* __restrict__ A, const float* __restrict__ Bt,
                     const float* __restrict__ bias, float* __restrict__ C,
                     int N, int K)
{
    __shared__ __align__(16) uint32_t sA[2][2048];   // 128 rows x 64 B
    __shared__ __align__(16) uint32_t sB[2][2048];

    const int bm   = blockIdx.y * 128;
    const int bn   = blockIdx.x * 128;
    const int tid  = threadIdx.x;
    const int lane = tid & 31;
    const int warp = tid >> 5;
    const int g    = lane >> 2;
    const int tig  = lane & 3;
    const int wm   = (warp >> 2) * 64;
    const int wn   = (warp & 3) * 32;

    // loader: thread -> rows lr, lr+64; chunk lc (8 fp16 = 8 floats of k)
    const int lr = tid >> 2;          // 0..63
    const int lc = tid & 3;           // chunk 0..3
    const int lkey = (lr >> 1) & 3;   // same key for lr and lr+64
    const uint32_t so1 = (uint32_t)(lr * 64        + ((lc ^ lkey) << 4));
    const uint32_t so2 = (uint32_t)((lr + 64) * 64 + ((lc ^ lkey) << 4));
    const float* Ap1 = A  + (size_t)(bm + lr) * K + lc * 8;
    const float* Ap2 = A  + (size_t)(bm + lr + 64) * K + lc * 8;
    const float* Bp1 = Bt + (size_t)(bn + lr) * K + lc * 8;
    const float* Bp2 = Bt + (size_t)(bn + lr + 64) * K + lc * 8;

    // ldmatrix addresses (byte offsets), k16-step 0 (chunks 0,1).
    // A x4: row +8 on lane bit3, chunk +1 on lane bit4.
    // B x4: chunk +1 on lane bit3, row +8 on lane bit4.
    const uint32_t aBase0 = smem_u32(&sA[0][0]);
    const uint32_t aBase1 = smem_u32(&sA[1][0]);
    const uint32_t bBase0 = smem_u32(&sB[0][0]);
    const uint32_t bBase1 = smem_u32(&sB[1][0]);
    const int r8 = lane & 7;
    uint32_t aoff[4], boff[2];
    #pragma unroll
    for (int mt = 0; mt < 4; mt++) {
        const int m = wm + mt * 16 + r8 + ((lane >> 3) & 1) * 8;
        const int c = lane >> 4;
        aoff[mt] = (uint32_t)(m * 64 + ((c ^ ((m >> 1) & 3)) << 4));
    }
    #pragma unroll
    for (int np = 0; np < 2; np++) {
        const int n = wn + np * 16 + r8 + (lane >> 4) * 8;
        const int c = (lane >> 3) & 1;
        boff[np] = (uint32_t)(n * 64 + ((c ^ ((n >> 1) & 3)) << 4));
    }

    float acc[4][4][4];
    #pragma unroll
    for (int a = 0; a < 4; a++)
        #pragma unroll
        for (int b = 0; b < 4; b++)
            #pragma unroll
            for (int c = 0; c < 4; c++) acc[a][b][c] = 0.f;

    float4 aA1, aA2, aB1, aB2, bA1, bA2, bB1, bB2;

    // prologue: tile 0 -> buf 0
    aA1 = __ldg((const float4*)Ap1);     aA2 = __ldg((const float4*)Ap1 + 1);
    bA1 = __ldg((const float4*)Ap2);     bA2 = __ldg((const float4*)Ap2 + 1);
    aB1 = __ldg((const float4*)Bp1);     aB2 = __ldg((const float4*)Bp1 + 1);
    bB1 = __ldg((const float4*)Bp2);     bB2 = __ldg((const float4*)Bp2 + 1);
    {
        uint4 w;
        w.x = pack_h2(aA1.x, aA1.y); w.y = pack_h2(aA1.z, aA1.w);
        w.z = pack_h2(aA2.x, aA2.y); w.w = pack_h2(aA2.z, aA2.w);
        *(uint4*)((char*)&sA[0][0] + so1) = w;
        w.x = pack_h2(bA1.x, bA1.y); w.y = pack_h2(bA1.z, bA1.w);
        w.z = pack_h2(bA2.x, bA2.y); w.w = pack_h2(bA2.z, bA2.w);
        *(uint4*)((char*)&sA[0][0] + so2) = w;
        w.x = pack_h2(aB1.x, aB1.y); w.y = pack_h2(aB1.z, aB1.w);
        w.z = pack_h2(aB2.x, aB2.y); w.w = pack_h2(aB2.z, aB2.w);
        *(uint4*)((char*)&sB[0][0] + so1) = w;
        w.x = pack_h2(bB1.x, bB1.y); w.y = pack_h2(bB1.z, bB1.w);
        w.z = pack_h2(bB2.x, bB2.y); w.w = pack_h2(bB2.z, bB2.w);
        *(uint4*)((char*)&sB[0][0] + so2) = w;
    }
    __syncthreads();

    const int T = K >> 5;   // BK = 32
    for (int t = 0; t < T; t++) {
        const int cur = t & 1;
        const uint32_t aB = cur ? aBase1 : aBase0;
        const uint32_t bB = cur ? bBase1 : bBase0;
        const bool more = (t + 1 < T);
        if (more) {
            const int k0 = (t + 1) << 5;
            aA1 = __ldg((const float4*)(Ap1 + k0));  aA2 = __ldg((const float4*)(Ap1 + k0) + 1);
            bA1 = __ldg((const float4*)(Ap2 + k0));  bA2 = __ldg((const float4*)(Ap2 + k0) + 1);
            aB1 = __ldg((const float4*)(Bp1 + k0));  aB2 = __ldg((const float4*)(Bp1 + k0) + 1);
            bB1 = __ldg((const float4*)(Bp2 + k0));  bB2 = __ldg((const float4*)(Bp2 + k0) + 1);
        }

        #pragma unroll
        for (int s = 0; s < 2; s++) {
            const uint32_t sx = (uint32_t)(s << 5);   // chunks +2 == XOR 32 bytes
            uint32_t afr[4][4], bfr[2][4];
            #pragma unroll
            for (int mt = 0; mt < 4; mt++)
                ldsm_x4(afr[mt], aB + (aoff[mt] ^ sx));
            #pragma unroll
            for (int np = 0; np < 2; np++)
                ldsm_x4(bfr[np], bB + (boff[np] ^ sx));
            #pragma unroll
            for (int mt = 0; mt < 4; mt++)
                #pragma unroll
                for (int nt = 0; nt < 4; nt++)
                    mma_f16(acc[mt][nt], afr[mt], &bfr[nt >> 1][(nt & 1) * 2]);
        }

        if (more) {
            const int nb = (t + 1) & 1;
            uint4 w;
            w.x = pack_h2(aA1.x, aA1.y); w.y = pack_h2(aA1.z, aA1.w);
            w.z = pack_h2(aA2.x, aA2.y); w.w = pack_h2(aA2.z, aA2.w);
            *(uint4*)((char*)&sA[nb][0] + so1) = w;
            w.x = pack_h2(bA1.x, bA1.y); w.y = pack_h2(bA1.z, bA1.w);
            w.z = pack_h2(bA2.x, bA2.y); w.w = pack_h2(bA2.z, bA2.w);
            *(uint4*)((char*)&sA[nb][0] + so2) = w;
            w.x = pack_h2(aB1.x, aB1.y); w.y = pack_h2(aB1.z, aB1.w);
            w.z = pack_h2(aB2.x, aB2.y); w.w = pack_h2(aB2.z, aB2.w);
            *(uint4*)((char*)&sB[nb][0] + so1) = w;
            w.x = pack_h2(bB1.x, bB1.y); w.y = pack_h2(bB1.z, bB1.w);
            w.z = pack_h2(bB2.x, bB2.y); w.w = pack_h2(bB2.z, bB2.w);
            *(uint4*)((char*)&sB[nb][0] + so2) = w;
        }
        __syncthreads();
    }

    // Epilogue: bias + store
    #pragma unroll
    for (int mt = 0; mt < 4; mt++) {
        #pragma unroll
        for (int nt = 0; nt < 4; nt++) {
            const int row0 = bm + wm + mt * 16 + g;
            const int col0 = bn + wn + nt * 8 + tig * 2;
            const float b0 = __ldg(bias + col0);
            const float b1 = __ldg(bias + col0 + 1);
            float2 r0, r1;
            r0.x = acc[mt][nt][0] + b0; r0.y = acc[mt][nt][1] + b1;
            r1.x = acc[mt][nt][2] + b0; r1.y = acc[mt][nt][3] + b1;
            *(float2*)(C + (size_t)row0 * N + col0)       = r0;
            *(float2*)(C + (size_t)(row0 + 8) * N + col0) = r1;
        }
    }
}

// ---------------------------------------------------------------------------
// Windowed attention via mma.sync tf32 (unchanged from R8/R9).
// Block = (head, window), 128 threads = 4 warps, warp w owns query rows
// [16w, 16w+16). S = Q*K^T (m64n64k32), softmax in accumulator layout,
// O = P*V (m64n32k64) with P staged through smem (overlaying Q/K).
//   pixel(h) = (wh*8 + ph + 4) & 63   (same for w)
// ---------------------------------------------------------------------------
__device__ __forceinline__ int pix_row(int win, int t) {
    const int b  = win >> 6;
    const int wi = win & 63;
    const int h  = (((wi >> 3) << 3) + (t >> 3) + 4) & 63;
    const int w  = (((wi & 7) << 3) + (t & 7) + 4) & 63;
    return (((b << 6) | h) << 6) | w;   // b*4096 + h*64 + w
}

__device__ __forceinline__ int qoff(int row, int dim) {   // 32-float rows
    return row * 32 + (((dim >> 2) ^ (row & 7)) << 2) + (dim & 3);
}
__device__ __forceinline__ int poff(int row, int col) {   // 64-float rows
    return row * 64 + (((col >> 2) ^ (row & 7)) << 2) + (col & 3);
}

__global__ __launch_bounds__(128)
void attn_mma_kernel(const float* __restrict__ qkv, const float* __restrict__ rel_pos,
                     float* __restrict__ att)
{
    const int head = blockIdx.x;
    const int win  = blockIdx.y;
    const int tid  = threadIdx.x;
    const int lane = tid & 31;
    const int g    = lane >> 2;
    const int tig  = lane & 3;
    const int m0   = (tid >> 5) * 16;

    __shared__ __align__(16) uint32_t sQK[4096];  // Q | K; reused as P[64][64]
    __shared__ __align__(16) uint32_t vst[2048];  // V^T: [dim][key], swizzled
    __shared__ float rp[225];

    for (int i = tid; i < 225; i += 128) rp[i] = __ldg(rel_pos + i * NHEADS + head);
    {
        const int row  = tid >> 1;
        const int half = tid & 1;
        const size_t base = (size_t)pix_row(win, row) * N_QKV + head * 32 + half * 16;
        const float4* qp = (const float4*)(qkv + base);
        const float4* kp = (const float4*)(qkv + base + 512);
        const float4* vp = (const float4*)(qkv + base + 1024);
        const float scale = 0.17677669529663687f;   // 1/sqrt(32)
        #pragma unroll
        for (int u = 0; u < 4; u++) {
            const int d0 = half * 16 + u * 4;
            float4 v4 = __ldg(qp + u);
            uint4 w;
            w.x = f2tf32(v4.x * scale); w.y = f2tf32(v4.y * scale);
            w.z = f2tf32(v4.z * scale); w.w = f2tf32(v4.w * scale);
            *(uint4*)&sQK[qoff(row, d0)] = w;
            v4 = __ldg(kp + u);
            w.x = f2tf32(v4.x); w.y = f2tf32(v4.y); w.z = f2tf32(v4.z); w.w = f2tf32(v4.w);
            *(uint4*)&sQK[2048 + qoff(row, d0)] = w;
            v4 = __ldg(vp + u);
            vst[poff(d0 + 0, row)] = f2tf32(v4.x);
            vst[poff(d0 + 1, row)] = f2tf32(v4.y);
            vst[poff(d0 + 2, row)] = f2tf32(v4.z);
            vst[poff(d0 + 3, row)] = f2tf32(v4.w);
        }
    }
    __syncthreads();

    float acc[8][4];
    #pragma unroll
    for (int nt = 0; nt < 8; nt++)
        #pragma unroll
        for (int c = 0; c < 4; c++) acc[nt][c] = 0.f;

    #pragma unroll
    for (int kt = 0; kt < 4; kt++) {
        uint32_t a[4];
        a[0] = sQK[qoff(m0 + g,     kt * 8 + tig)];
        a[1] = sQK[qoff(m0 + g + 8, kt * 8 + tig)];
        a[2] = sQK[qoff(m0 + g,     kt * 8 + tig + 4)];
        a[3] = sQK[qoff(m0 + g + 8, kt * 8 + tig + 4)];
        #pragma unroll
        for (int nt = 0; nt < 8; nt++) {
            uint32_t b[2];
            b[0] = sQK[2048 + qoff(nt * 8 + g, kt * 8 + tig)];
            b[1] = sQK[2048 + qoff(nt * 8 + g, kt * 8 + tig + 4)];
            mma_tf32(acc[nt], a, b);
        }
    }

    const int i0 = m0 + g;
    const int yi = i0 >> 3, xi = i0 & 7;
    float mx0 = -1e30f, mx1 = -1e30f;
    #pragma unroll
    for (int nt = 0; nt < 8; nt++) {
        const int bi = (yi - nt + 7) * 15 + (xi - 2 * tig + 7);
        acc[nt][0] += rp[bi];
        acc[nt][1] += rp[bi - 1];
        acc[nt][2] += rp[bi + 15];
        acc[nt][3] += rp[bi + 14];
        mx0 = fmaxf(mx0, fmaxf(acc[nt][0], acc[nt][1]));
        mx1 = fmaxf(mx1, fmaxf(acc[nt][2], acc[nt][3]));
    }
    mx0 = fmaxf(mx0, __shfl_xor_sync(0xffffffffu, mx0, 1));
    mx0 = fmaxf(mx0, __shfl_xor_sync(0xffffffffu, mx0, 2));
    mx1 = fmaxf(mx1, __shfl_xor_sync(0xffffffffu, mx1, 1));
    mx1 = fmaxf(mx1, __shfl_xor_sync(0xffffffffu, mx1, 2));

    float s0 = 0.f, s1 = 0.f;
    #pragma unroll
    for (int nt = 0; nt < 8; nt++) {
        acc[nt][0] = __expf(acc[nt][0] - mx0);
        acc[nt][1] = __expf(acc[nt][1] - mx0);
        acc[nt][2] = __expf(acc[nt][2] - mx1);
        acc[nt][3] = __expf(acc[nt][3] - mx1);
        s0 += acc[nt][0] + acc[nt][1];
        s1 += acc[nt][2] + acc[nt][3];
    }
    s0 += __shfl_xor_sync(0xffffffffu, s0, 1);
    s0 += __shfl_xor_sync(0xffffffffu, s0, 2);
    s1 += __shfl_xor_sync(0xffffffffu, s1, 1);
    s1 += __shfl_xor_sync(0xffffffffu, s1, 2);
    const float inv0 = 1.0f / s0;
    const float inv1 = 1.0f / s1;

    __syncthreads();
    #pragma unroll
    for (int nt = 0; nt < 8; nt++) {
        const int o0 = poff(i0,     nt * 8 + 2 * tig);
        const int o1 = poff(i0 + 8, nt * 8 + 2 * tig);
        sQK[o0]     = f2tf32(acc[nt][0] * inv0);
        sQK[o0 + 1] = f2tf32(acc[nt][1] * inv0);
        sQK[o1]     = f2tf32(acc[nt][2] * inv1);
        sQK[o1 + 1] = f2tf32(acc[nt][3] * inv1);
    }
    __syncwarp();

    float accO[4][4];
    #pragma unroll
    for (int nt = 0; nt < 4; nt++)
        #pragma unroll
        for (int c = 0; c < 4; c++) accO[nt][c] = 0.f;

    #pragma unroll
    for (int kt = 0; kt < 8; kt++) {
        uint32_t a[4];
        a[0] = sQK[poff(m0 + g,     kt * 8 + tig)];
        a[1] = sQK[poff(m0 + g + 8, kt * 8 + tig)];
        a[2] = sQK[poff(m0 + g,     kt * 8 + tig + 4)];
        a[3] = sQK[poff(m0 + g + 8, kt * 8 + tig + 4)];
        #pragma unroll
        for (int nt = 0; nt < 4; nt++) {
            uint32_t b[2];
            b[0] = vst[poff(nt * 8 + g, kt * 8 + tig)];
            b[1] = vst[poff(nt * 8 + g, kt * 8 + tig + 4)];
            mma_tf32(accO[nt], a, b);
        }
    }

    {
        const size_t r0 = (size_t)pix_row(win, i0)     * N_OUT + head * 32;
        const size_t r1 = (size_t)pix_row(win, i0 + 8) * N_OUT + head * 32;
        #pragma unroll
        for (int nt = 0; nt < 4; nt++) {
            float2 w0, w1;
            w0.x = accO[nt][0]; w0.y = accO[nt][1];
            w1.x = accO[nt][2]; w1.y = accO[nt][3];
            *(float2*)(att + r0 + nt * 8 + 2 * tig) = w0;
            *(float2*)(att + r1 + nt * 8 + 2 * tig) = w1;
        }
    }
}

// ---------------------------------------------------------------------------
extern "C" void kernel_launch(void* const* d_in, const int* in_sizes, int n_in,
                              void* d_out, int out_size)
{
    const float* x       = (const float*)d_in[0];
    const float* w_qkv   = (const float*)d_in[1];
    const float* b_qkv   = (const float*)d_in[2];
    const float* rel_pos = (const float*)d_in[3];
    const float* w_out   = (const float*)d_in[4];
    const float* b_out   = (const float*)d_in[5];
    float* out = (float*)d_out;

    float *qkv = nullptr, *att = nullptr, *btq = nullptr, *bto = nullptr;
    cudaGetSymbolAddress((void**)&qkv, g_qkv);
    cudaGetSymbolAddress((void**)&att, g_att);
    cudaGetSymbolAddress((void**)&btq, g_btq);
    cudaGetSymbolAddress((void**)&bto, g_bto);

    // 0) transpose weights to K-major (tiny, once per launch)
    transpose_kernel<<<dim3(N_QKV / 32, KDIM / 32), dim3(32, 8)>>>(w_qkv, btq, KDIM, N_QKV);
    transpose_kernel<<<dim3(N_OUT / 32, KDIM / 32), dim3(32, 8)>>>(w_out, bto, KDIM, N_OUT);

    // 1) QKV projection (fp16 tensor cores)
    gemm_f16_kernel<<<dim3(N_QKV / 128, M_TOK / 128), 256>>>(
        x, btq, b_qkv, qkv, N_QKV, KDIM);

    // 2) Shifted-window attention (tf32 tensor cores)
    attn_mma_kernel<<<dim3(NHEADS, 1024), dim3(128)>>>(qkv, rel_pos, att);

    // 3) Output projection (fp16 tensor cores, writes final output)
    gemm_f16_kernel<<<dim3(N_OUT / 128, M_TOK / 128), 256>>>(
        att, bto, b_out, out, N_OUT, KDIM);
}

// round 14
// speedup vs baseline: 2.8945x; 1.4342x over previous
#include <cuda_runtime.h>
#include <cuda_fp16.h>
#include <cstdint>
#include <cstddef>

// Problem constants (fixed by the benchmark)
//  x: (16, 64, 64, 512)  -> 65536 tokens x 512 ch
//  w_qkv: (512, 1536), b_qkv: (1536)
//  rel_pos: (225, 16)
//  w_out: (512, 512), b_out: (512)
//  window 8x8, shift 4, 16 heads, head_dim 32

#define M_TOK   65536
#define KDIM    512
#define N_QKV   1536
#define N_OUT   512
#define NHEADS  16

// Scratch (allocation-free rule: __device__ globals)
static __device__ __half g_xh  [(size_t)M_TOK * KDIM];    // 64 MB  (x as fp16)
static __device__ __half g_qkvh[(size_t)M_TOK * N_QKV];   // 192 MB
static __device__ __half g_atth[(size_t)M_TOK * N_OUT];   // 64 MB
static __device__ __half g_btqh[(size_t)N_QKV * KDIM];    // 1.5 MB (w_qkv^T fp16)
static __device__ __half g_btoh[(size_t)N_OUT * KDIM];    // 0.5 MB (w_out^T fp16)

// pack two floats into f16x2 (lo in low 16 bits)
__device__ __forceinline__ uint32_t pack_h2(float lo, float hi) {
    uint32_t r;
    asm("cvt.rn.f16x2.f32 %0, %1, %2;" : "=r"(r) : "f"(hi), "f"(lo));
    return r;
}

__device__ __forceinline__ uint32_t smem_u32(const void* p) {
    uint32_t a;
    asm("{ .reg .u64 t; cvta.to.shared.u64 t, %1; cvt.u32.u64 %0, t; }" : "=r"(a) : "l"(p));
    return a;
}

__device__ __forceinline__ void mma_f16(float* d, const uint32_t* a, const uint32_t* b) {
    asm volatile(
        "mma.sync.aligned.m16n8k16.row.col.f32.f16.f16.f32 "
        "{%0,%1,%2,%3}, {%4,%5,%6,%7}, {%8,%9}, {%0,%1,%2,%3};\n"
        : "+f"(d[0]), "+f"(d[1]), "+f"(d[2]), "+f"(d[3])
        : "r"(a[0]), "r"(a[1]), "r"(a[2]), "r"(a[3]),
          "r"(b[0]), "r"(b[1]));
}

__device__ __forceinline__ void ldsm_x4(uint32_t* r, uint32_t saddr) {
    asm volatile("ldmatrix.sync.aligned.m8n8.x4.shared.b16 {%0,%1,%2,%3}, [%4];"
                 : "=r"(r[0]), "=r"(r[1]), "=r"(r[2]), "=r"(r[3]) : "r"(saddr));
}
__device__ __forceinline__ void ldsm_x4_t(uint32_t* r, uint32_t saddr) {
    asm volatile("ldmatrix.sync.aligned.m8n8.x4.trans.shared.b16 {%0,%1,%2,%3}, [%4];"
                 : "=r"(r[0]), "=r"(r[1]), "=r"(r[2]), "=r"(r[3]) : "r"(saddr));
}

// ---------------------------------------------------------------------------
// fp32 -> fp16 bulk convert (8 elems / thread)
// ---------------------------------------------------------------------------
__global__ __launch_bounds__(256)
void f2h_kernel(const float* __restrict__ in, __half* __restrict__ out, size_t n8) {
    const size_t i = (size_t)blockIdx.x * blockDim.x + threadIdx.x;
    if (i >= n8) return;
    const float4* p = (const float4*)in + i * 2;
    float4 a = __ldg(p), b = __ldg(p + 1);
    uint2 w;
    w.x = pack_h2(a.x, a.y);  w.y = pack_h2(a.z, a.w);
    uint2 v;
    v.x = pack_h2(b.x, b.y);  v.y = pack_h2(b.z, b.w);
    uint4 o = make_uint4(w.x, w.y, v.x, v.y);
    *((uint4*)out + i) = o;
}

// ---------------------------------------------------------------------------
// Weight transpose + fp16: out[c][r] = (half)in[r][c].  R, C multiples of 32.
// ---------------------------------------------------------------------------
__global__ void transpose_h_kernel(const float* __restrict__ in, __half* __restrict__ out,
                                   int R, int C) {
    __shared__ float t[32][33];
    const int c0 = blockIdx.x * 32, r0 = blockIdx.y * 32;
    const int x = threadIdx.x, y = threadIdx.y;
    #pragma unroll
    for (int dy = 0; dy < 32; dy += 8)
        t[y + dy][x] = in[(size_t)(r0 + y + dy) * C + c0 + x];
    __syncthreads();
    #pragma unroll
    for (int dy = 0; dy < 32; dy += 8)
        out[(size_t)(c0 + y + dy) * R + r0 + x] = __float2half(t[x][y + dy]);
}

// ---------------------------------------------------------------------------
// Dense GEMM: C[M,N] = A[M,K]*B[K,N] + bias[N]; A, Bt fp16 (Bt = B^T, K-major),
// fp16 mma.sync m16n8k16 (fp32 accum). BM=128, BN=128, BK=32, 256 threads,
// double-buffered smem, no in-loop converts (LDG.128 -> STS.128).
// Smem tile rows: 32 fp16 = 64 B = 4 x 16B chunks, XOR swizzle
//   chunk' = chunk ^ ((row>>1)&3)  (STS + all ldmatrix phases conflict-free).
// CT = half (packed h2 stores) or float.
// ---------------------------------------------------------------------------
template <typename CT>
__global__ __launch_bounds__(256, 2)
void gemm_h_kernel(const __half* __restrict__ A, const __half* __restrict__ Bt,
                   const float* __restrict__ bias, CT* __restrict__ C,
                   int N, int K)
{
    __shared__ __align__(16) uint32_t sA[2][2048];   // 128 rows x 64 B
    __shared__ __align__(16) uint32_t sB[2][2048];

    const int bm   = blockIdx.y * 128;
    const int bn   = blockIdx.x * 128;
    const int tid  = threadIdx.x;
    const int lane = tid & 31;
    const int warp = tid >> 5;
    const int g    = lane >> 2;
    const int tig  = lane & 3;
    const int wm   = (warp >> 2) * 64;
    const int wn   = (warp & 3) * 32;

    // loader: thread -> rows lr, lr+64; 16B chunk lc (8 fp16)
    const int lr = tid >> 2;
    const int lc = tid & 3;
    const int lkey = (lr >> 1) & 3;
    const uint32_t so1 = (uint32_t)(lr * 64        + ((lc ^ lkey) << 4));
    const uint32_t so2 = (uint32_t)((lr + 64) * 64 + ((lc ^ lkey) << 4));
    const __half* Ap1 = A  + (size_t)(bm + lr) * K + lc * 8;
    const __half* Ap2 = A  + (size_t)(bm + lr + 64) * K + lc * 8;
    const __half* Bp1 = Bt + (size_t)(bn + lr) * K + lc * 8;
    const __half* Bp2 = Bt + (size_t)(bn + lr + 64) * K + lc * 8;

    const uint32_t aBase0 = smem_u32(&sA[0][0]);
    const uint32_t aBase1 = smem_u32(&sA[1][0]);
    const uint32_t bBase0 = smem_u32(&sB[0][0]);
    const uint32_t bBase1 = smem_u32(&sB[1][0]);
    const int r8 = lane & 7;
    uint32_t aoff[4], boff[2];
    #pragma unroll
    for (int mt = 0; mt < 4; mt++) {
        const int m = wm + mt * 16 + r8 + ((lane >> 3) & 1) * 8;
        const int c = lane >> 4;
        aoff[mt] = (uint32_t)(m * 64 + ((c ^ ((m >> 1) & 3)) << 4));
    }
    #pragma unroll
    for (int np = 0; np < 2; np++) {
        const int n = wn + np * 16 + r8 + (lane >> 4) * 8;
        const int c = (lane >> 3) & 1;
        boff[np] = (uint32_t)(n * 64 + ((c ^ ((n >> 1) & 3)) << 4));
    }

    float acc[4][4][4];
    #pragma unroll
    for (int a = 0; a < 4; a++)
        #pragma unroll
        for (int b = 0; b < 4; b++)
            #pragma unroll
            for (int c = 0; c < 4; c++) acc[a][b][c] = 0.f;

    uint4 va1, va2, vb1, vb2;

    // prologue: tile 0 -> buf 0
    va1 = __ldg((const uint4*)Ap1);
    va2 = __ldg((const uint4*)Ap2);
    vb1 = __ldg((const uint4*)Bp1);
    vb2 = __ldg((const uint4*)Bp2);
    *(uint4*)((char*)&sA[0][0] + so1) = va1;
    *(uint4*)((char*)&sA[0][0] + so2) = va2;
    *(uint4*)((char*)&sB[0][0] + so1) = vb1;
    *(uint4*)((char*)&sB[0][0] + so2) = vb2;
    __syncthreads();

    const int T = K >> 5;   // BK = 32
    for (int t = 0; t < T; t++) {
        const int cur = t & 1;
        const uint32_t aB = cur ? aBase1 : aBase0;
        const uint32_t bB = cur ? bBase1 : bBase0;
        const bool more = (t + 1 < T);
        if (more) {
            const int k0 = (t + 1) << 5;
            va1 = __ldg((const uint4*)(Ap1 + k0));
            va2 = __ldg((const uint4*)(Ap2 + k0));
            vb1 = __ldg((const uint4*)(Bp1 + k0));
            vb2 = __ldg((const uint4*)(Bp2 + k0));
        }

        #pragma unroll
        for (int s = 0; s < 2; s++) {
            const uint32_t sx = (uint32_t)(s << 5);   // chunk +2 == XOR 32 bytes
            uint32_t afr[4][4], bfr[2][4];
            #pragma unroll
            for (int mt = 0; mt < 4; mt++)
                ldsm_x4(afr[mt], aB + (aoff[mt] ^ sx));
            #pragma unroll
            for (int np = 0; np < 2; np++)
                ldsm_x4(bfr[np], bB + (boff[np] ^ sx));
            #pragma unroll
            for (int mt = 0; mt < 4; mt++)
                #pragma unroll
                for (int nt = 0; nt < 4; nt++)
                    mma_f16(acc[mt][nt], afr[mt], &bfr[nt >> 1][(nt & 1) * 2]);
        }

        if (more) {
            const int nb = (t + 1) & 1;
            uint32_t* sAp = cur ? &sA[0][0] : &sA[1][0];
            uint32_t* sBp = cur ? &sB[0][0] : &sB[1][0];
            (void)nb;
            *(uint4*)((char*)sAp + so1) = va1;
            *(uint4*)((char*)sAp + so2) = va2;
            *(uint4*)((char*)sBp + so1) = vb1;
            *(uint4*)((char*)sBp + so2) = vb2;
        }
        __syncthreads();
    }

    // Epilogue: bias + store
    #pragma unroll
    for (int mt = 0; mt < 4; mt++) {
        #pragma unroll
        for (int nt = 0; nt < 4; nt++) {
            const int row0 = bm + wm + mt * 16 + g;
            const int col0 = bn + wn + nt * 8 + tig * 2;
            const float b0 = __ldg(bias + col0);
            const float b1 = __ldg(bias + col0 + 1);
            if constexpr (sizeof(CT) == 2) {
                *(uint32_t*)((__half*)C + (size_t)row0 * N + col0) =
                    pack_h2(acc[mt][nt][0] + b0, acc[mt][nt][1] + b1);
                *(uint32_t*)((__half*)C + (size_t)(row0 + 8) * N + col0) =
                    pack_h2(acc[mt][nt][2] + b0, acc[mt][nt][3] + b1);
            } else {
                float2 r0, r1;
                r0.x = acc[mt][nt][0] + b0; r0.y = acc[mt][nt][1] + b1;
                r1.x = acc[mt][nt][2] + b0; r1.y = acc[mt][nt][3] + b1;
                *(float2*)((float*)C + (size_t)row0 * N + col0)       = r0;
                *(float2*)((float*)C + (size_t)(row0 + 8) * N + col0) = r1;
            }
        }
    }
}

// ---------------------------------------------------------------------------
// Windowed attention, full fp16 mma.sync.
// Block = (head, window), 128 threads = 4 warps, warp w owns query rows
// [16w, 16w+16). S = Q*K^T (k16 x2), softmax in accumulator layout (scale
// folded into bias FFMA), P packed to fp16 smem, O = P*V with V consumed in
// natural (key-major) layout via ldmatrix.trans.
//   pixel(h) = (wh*8 + ph + 4) & 63   (same for w)
// ---------------------------------------------------------------------------
__device__ __forceinline__ int pix_row(int win, int t) {
    const int b  = win >> 6;
    const int wi = win & 63;
    const int h  = (((wi >> 3) << 3) + (t >> 3) + 4) & 63;
    const int w  = (((wi & 7) << 3) + (t & 7) + 4) & 63;
    return (((b << 6) | h) << 6) | w;   // b*4096 + h*64 + w
}

__global__ __launch_bounds__(128)
void attn_h_kernel(const __half* __restrict__ qkv, const float* __restrict__ rel_pos,
                   __half* __restrict__ att)
{
    const int head = blockIdx.x;
    const int win  = blockIdx.y;
    const int tid  = threadIdx.x;
    const int lane = tid & 31;
    const int g    = lane >> 2;
    const int tig  = lane & 3;
    const int m0   = (tid >> 5) * 16;

    // 64 rows x 32 fp16 = 64 B rows (4 chunks), swizzle c^((r>>1)&3)
    __shared__ __align__(16) char sQ[4096];
    __shared__ __align__(16) char sK[4096];
    __shared__ __align__(16) char sV[4096];
    // P: 64 rows x 64 fp16 = 128 B rows (8 chunks), swizzle c^(r&7)
    __shared__ __align__(16) char sP[8192];
    __shared__ float rp[225];

    const uint32_t qB = smem_u32(sQ);
    const uint32_t kB = smem_u32(sK);
    const uint32_t vB = smem_u32(sV);
    const uint32_t pB = smem_u32(sP);

    // ---- stage (fp16 passthrough, no converts) ----
    for (int i = tid; i < 225; i += 128) rp[i] = __ldg(rel_pos + i * NHEADS + head);
    {
        const int row  = tid >> 1;
        const int half = tid & 1;
        const size_t base = (size_t)pix_row(win, row) * N_QKV + head * 32;
        const uint4* qp = (const uint4*)(qkv + base);
        const uint4* kp = (const uint4*)(qkv + base + 512);
        const uint4* vp = (const uint4*)(qkv + base + 1024);
        const int key = (row >> 1) & 3;
        #pragma unroll
        for (int u = 0; u < 2; u++) {
            const int c = half * 2 + u;
            const uint32_t sw = (uint32_t)(row * 64 + ((c ^ key) << 4));
            *(uint4*)(sQ + sw) = __ldg(qp + c);
            *(uint4*)(sK + sw) = __ldg(kp + c);
            *(uint4*)(sV + sw) = __ldg(vp + c);
        }
    }
    __syncthreads();

    // fragment address bases
    const int r8 = lane & 7;
    uint32_t aoffQ, boffK[4];
    {
        const int m = m0 + r8 + ((lane >> 3) & 1) * 8;
        const int c = lane >> 4;
        aoffQ = (uint32_t)(m * 64 + ((c ^ ((m >> 1) & 3)) << 4));
    }
    #pragma unroll
    for (int nb = 0; nb < 4; nb++) {
        const int n = nb * 16 + r8 + (lane >> 4) * 8;
        const int c = (lane >> 3) & 1;
        boffK[nb] = (uint32_t)(n * 64 + ((c ^ ((n >> 1) & 3)) << 4));
    }

    // ---- S = Q*K^T  (m16 n64 k32 per warp; 2 k16 steps) ----
    float acc[8][4];
    #pragma unroll
    for (int nt = 0; nt < 8; nt++)
        #pragma unroll
        for (int c = 0; c < 4; c++) acc[nt][c] = 0.f;

    #pragma unroll
    for (int kt = 0; kt < 2; kt++) {
        const uint32_t sx = (uint32_t)(kt << 5);
        uint32_t a[4];
        ldsm_x4(a, qB + (aoffQ ^ sx));
        #pragma unroll
        for (int nb = 0; nb < 4; nb++) {
            uint32_t b[4];
            ldsm_x4(b, kB + (boffK[nb] ^ sx));
            mma_f16(acc[nb * 2],     a, b);
            mma_f16(acc[nb * 2 + 1], a, b + 2);
        }
    }

    // ---- scale + bias + softmax (rows i0 = m0+g and i0+8) ----
    const float scale = 0.17677669529663687f;   // 1/sqrt(32)
    const int i0 = m0 + g;
    const int yi = i0 >> 3, xi = i0 & 7;
    float mx0 = -1e30f, mx1 = -1e30f;
    #pragma unroll
    for (int nt = 0; nt < 8; nt++) {
        const int bi = (yi - nt + 7) * 15 + (xi - 2 * tig + 7);
        acc[nt][0] = fmaf(acc[nt][0], scale, rp[bi]);
        acc[nt][1] = fmaf(acc[nt][1], scale, rp[bi - 1]);
        acc[nt][2] = fmaf(acc[nt][2], scale, rp[bi + 15]);
        acc[nt][3] = fmaf(acc[nt][3], scale, rp[bi + 14]);
        mx0 = fmaxf(mx0, fmaxf(acc[nt][0], acc[nt][1]));
        mx1 = fmaxf(mx1, fmaxf(acc[nt][2], acc[nt][3]));
    }
    mx0 = fmaxf(mx0, __shfl_xor_sync(0xffffffffu, mx0, 1));
    mx0 = fmaxf(mx0, __shfl_xor_sync(0xffffffffu, mx0, 2));
    mx1 = fmaxf(mx1, __shfl_xor_sync(0xffffffffu, mx1, 1));
    mx1 = fmaxf(mx1, __shfl_xor_sync(0xffffffffu, mx1, 2));

    float s0 = 0.f, s1 = 0.f;
    #pragma unroll
    for (int nt = 0; nt < 8; nt++) {
        acc[nt][0] = __expf(acc[nt][0] - mx0);
        acc[nt][1] = __expf(acc[nt][1] - mx0);
        acc[nt][2] = __expf(acc[nt][2] - mx1);
        acc[nt][3] = __expf(acc[nt][3] - mx1);
        s0 += acc[nt][0] + acc[nt][1];
        s1 += acc[nt][2] + acc[nt][3];
    }
    s0 += __shfl_xor_sync(0xffffffffu, s0, 1);
    s0 += __shfl_xor_sync(0xffffffffu, s0, 2);
    s1 += __shfl_xor_sync(0xffffffffu, s1, 1);
    s1 += __shfl_xor_sync(0xffffffffu, s1, 2);
    const float inv0 = 1.0f / s0;
    const float inv1 = 1.0f / s1;

    // ---- stage P as fp16 (own rows only; no cross-warp hazard) ----
    {
        const int keyP = i0 & 7;   // same for i0 and i0+8
        #pragma unroll
        for (int nt = 0; nt < 8; nt++) {
            const uint32_t a0 = (uint32_t)(i0 * 128       + ((nt ^ keyP) << 4) + 4 * tig);
            const uint32_t a1 = (uint32_t)((i0 + 8) * 128 + ((nt ^ keyP) << 4) + 4 * tig);
            *(uint32_t*)(sP + a0) = pack_h2(acc[nt][0] * inv0, acc[nt][1] * inv0);
            *(uint32_t*)(sP + a1) = pack_h2(acc[nt][2] * inv1, acc[nt][3] * inv1);
        }
    }
    __syncwarp();

    // ---- O = P*V  (m16 n32 k64 per warp; 4 k16 steps, trans-ldsm V) ----
    float accO[4][4];
    #pragma unroll
    for (int nt = 0; nt < 4; nt++)
        #pragma unroll
        for (int c = 0; c < 4; c++) accO[nt][c] = 0.f;

    uint32_t aoffP;
    {
        const int m = m0 + r8 + ((lane >> 3) & 1) * 8;
        const int c = lane >> 4;            // k-chunk bit within k16
        aoffP = (uint32_t)(m * 128 + ((c ^ (m & 7)) << 4));
    }
    uint32_t voff[2];
    {
        const int rb  = r8 + ((lane >> 3) & 1) * 8;   // key row base 0..15
        const int key = (rb >> 1) & 3;                // kt*16 doesn't affect key
        #pragma unroll
        for (int nb = 0; nb < 2; nb++) {
            const int c = nb * 2 + (lane >> 4);
            voff[nb] = (uint32_t)(rb * 64 + ((c ^ key) << 4));
        }
    }

    #pragma unroll
    for (int kt = 0; kt < 4; kt++) {
        uint32_t a[4];
        ldsm_x4(a, pB + (aoffP ^ ((uint32_t)kt << 5)));
        #pragma unroll
        for (int nb = 0; nb < 2; nb++) {
            uint32_t b[4];
            ldsm_x4_t(b, vB + voff[nb] + (uint32_t)kt * 1024);
            mma_f16(accO[nb * 2],     a, b);
            mma_f16(accO[nb * 2 + 1], a, b + 2);
        }
    }

    // ---- epilogue: packed fp16 stores ----
    {
        const size_t r0 = (size_t)pix_row(win, i0)     * N_OUT + head * 32;
        const size_t r1 = (size_t)pix_row(win, i0 + 8) * N_OUT + head * 32;
        #pragma unroll
        for (int nt = 0; nt < 4; nt++) {
            *(uint32_t*)(att + r0 + nt * 8 + 2 * tig) = pack_h2(accO[nt][0], accO[nt][1]);
            *(uint32_t*)(att + r1 + nt * 8 + 2 * tig) = pack_h2(accO[nt][2], accO[nt][3]);
        }
    }
}

// ---------------------------------------------------------------------------
extern "C" void kernel_launch(void* const* d_in, const int* in_sizes, int n_in,
                              void* d_out, int out_size)
{
    const float* x       = (const float*)d_in[0];
    const float* w_qkv   = (const float*)d_in[1];
    const float* b_qkv   = (const float*)d_in[2];
    const float* rel_pos = (const float*)d_in[3];
    const float* w_out   = (const float*)d_in[4];
    const float* b_out   = (const float*)d_in[5];
    float* out = (float*)d_out;

    __half *xh, *qkvh, *atth, *btqh, *btoh;
    cudaGetSymbolAddress((void**)&xh,   g_xh);
    cudaGetSymbolAddress((void**)&qkvh, g_qkvh);
    cudaGetSymbolAddress((void**)&atth, g_atth);
    cudaGetSymbolAddress((void**)&btqh, g_btqh);
    cudaGetSymbolAddress((void**)&btoh, g_btoh);

    // 0) convert inputs to fp16 once per launch
    {
        const size_t n8 = (size_t)M_TOK * KDIM / 8;
        f2h_kernel<<<(unsigned)((n8 + 255) / 256), 256>>>(x, xh, n8);
    }
    transpose_h_kernel<<<dim3(N_QKV / 32, KDIM / 32), dim3(32, 8)>>>(w_qkv, btqh, KDIM, N_QKV);
    transpose_h_kernel<<<dim3(N_OUT / 32, KDIM / 32), dim3(32, 8)>>>(w_out, btoh, KDIM, N_OUT);

    // 1) QKV projection (fp16 in/out)
    gemm_h_kernel<__half><<<dim3(N_QKV / 128, M_TOK / 128), 256>>>(
        xh, btqh, b_qkv, qkvh, N_QKV, KDIM);

    // 2) Shifted-window attention (fp16 in/out)
    attn_h_kernel<<<dim3(NHEADS, 1024), dim3(128)>>>(qkvh, rel_pos, atth);

    // 3) Output projection (fp16 in, fp32 out)
    gemm_h_kernel<float><<<dim3(N_OUT / 128, M_TOK / 128), 256>>>(
        atth, btoh, b_out, out, N_OUT, KDIM);
}

// round 15
// speedup vs baseline: 3.4078x; 1.1773x over previous
#include <cuda_runtime.h>
#include <cuda_fp16.h>
#include <cstdint>
#include <cstddef>

// Problem constants (fixed by the benchmark)
//  x: (16, 64, 64, 512)  -> 65536 tokens x 512 ch
//  w_qkv: (512, 1536), b_qkv: (1536)
//  rel_pos: (225, 16)
//  w_out: (512, 512), b_out: (512)
//  window 8x8, shift 4, 16 heads, head_dim 32

#define M_TOK   65536
#define KDIM    512
#define N_QKV   1536
#define N_OUT   512
#define NHEADS  16

// Scratch (allocation-free rule: __device__ globals)
static __device__ __half g_xh  [(size_t)M_TOK * KDIM];    // 64 MB  (x as fp16)
static __device__ __half g_qkvh[(size_t)M_TOK * N_QKV];   // 192 MB
static __device__ __half g_atth[(size_t)M_TOK * N_OUT];   // 64 MB
static __device__ __half g_btqh[(size_t)N_QKV * KDIM];    // 1.5 MB (w_qkv^T fp16)
static __device__ __half g_btoh[(size_t)N_OUT * KDIM];    // 0.5 MB (w_out^T fp16)

// pack two floats into f16x2 (lo in low 16 bits)
__device__ __forceinline__ uint32_t pack_h2(float lo, float hi) {
    uint32_t r;
    asm("cvt.rn.f16x2.f32 %0, %1, %2;" : "=r"(r) : "f"(hi), "f"(lo));
    return r;
}

__device__ __forceinline__ uint32_t smem_u32(const void* p) {
    uint32_t a;
    asm("{ .reg .u64 t; cvta.to.shared.u64 t, %1; cvt.u32.u64 %0, t; }" : "=r"(a) : "l"(p));
    return a;
}

__device__ __forceinline__ void mma_f16(float* d, const uint32_t* a, const uint32_t* b) {
    asm volatile(
        "mma.sync.aligned.m16n8k16.row.col.f32.f16.f16.f32 "
        "{%0,%1,%2,%3}, {%4,%5,%6,%7}, {%8,%9}, {%0,%1,%2,%3};\n"
        : "+f"(d[0]), "+f"(d[1]), "+f"(d[2]), "+f"(d[3])
        : "r"(a[0]), "r"(a[1]), "r"(a[2]), "r"(a[3]),
          "r"(b[0]), "r"(b[1]));
}

__device__ __forceinline__ void ldsm_x4(uint32_t* r, uint32_t saddr) {
    asm volatile("ldmatrix.sync.aligned.m8n8.x4.shared.b16 {%0,%1,%2,%3}, [%4];"
                 : "=r"(r[0]), "=r"(r[1]), "=r"(r[2]), "=r"(r[3]) : "r"(saddr));
}
__device__ __forceinline__ void ldsm_x4_t(uint32_t* r, uint32_t saddr) {
    asm volatile("ldmatrix.sync.aligned.m8n8.x4.trans.shared.b16 {%0,%1,%2,%3}, [%4];"
                 : "=r"(r[0]), "=r"(r[1]), "=r"(r[2]), "=r"(r[3]) : "r"(saddr));
}

__device__ __forceinline__ void cp_async16(uint32_t dst, const void* src) {
    asm volatile("cp.async.cg.shared.global [%0], [%1], 16;\n" :: "r"(dst), "l"(src));
}
__device__ __forceinline__ void cp_commit() {
    asm volatile("cp.async.commit_group;\n" ::: "memory");
}
template <int N>
__device__ __forceinline__ void cp_wait() {
    asm volatile("cp.async.wait_group %0;\n" :: "n"(N) : "memory");
}

// ---------------------------------------------------------------------------
// fp32 -> fp16 bulk convert (8 elems / thread)
// ---------------------------------------------------------------------------
__global__ __launch_bounds__(256)
void f2h_kernel(const float* __restrict__ in, __half* __restrict__ out, size_t n8) {
    const size_t i = (size_t)blockIdx.x * blockDim.x + threadIdx.x;
    if (i >= n8) return;
    const float4* p = (const float4*)in + i * 2;
    float4 a = __ldg(p), b = __ldg(p + 1);
    uint4 o;
    o.x = pack_h2(a.x, a.y);  o.y = pack_h2(a.z, a.w);
    o.z = pack_h2(b.x, b.y);  o.w = pack_h2(b.z, b.w);
    *((uint4*)out + i) = o;
}

// ---------------------------------------------------------------------------
// Weight transpose + fp16: out[c][r] = (half)in[r][c].  R, C multiples of 32.
// ---------------------------------------------------------------------------
__global__ void transpose_h_kernel(const float* __restrict__ in, __half* __restrict__ out,
                                   int R, int C) {
    __shared__ float t[32][33];
    const int c0 = blockIdx.x * 32, r0 = blockIdx.y * 32;
    const int x = threadIdx.x, y = threadIdx.y;
    #pragma unroll
    for (int dy = 0; dy < 32; dy += 8)
        t[y + dy][x] = in[(size_t)(r0 + y + dy) * C + c0 + x];
    __syncthreads();
    #pragma unroll
    for (int dy = 0; dy < 32; dy += 8)
        out[(size_t)(c0 + y + dy) * R + r0 + x] = __float2half(t[x][y + dy]);
}

// ---------------------------------------------------------------------------
// Dense GEMM: C[M,N] = A[M,K]*B[K,N] + bias[N]; A, Bt fp16 (Bt = B^T, K-major),
// fp16 mma.sync m16n8k16 (fp32 accum).
// BM=128, BN=128, BK=32, 128 threads = 4 warps, warp tile 64x64 (2x2 grid).
// 3-stage cp.async.cg pipeline (L1-bypass staging), one syncthreads/tile.
// Smem rows: 32 fp16 = 64 B = 4 x 16B chunks, XOR swizzle c^((row>>1)&3).
// CT = half (packed h2 stores) or float.
// ---------------------------------------------------------------------------
#define GSTAGES 3

template <typename CT>
__global__ __launch_bounds__(128, 2)
void gemm_h_kernel(const __half* __restrict__ A, const __half* __restrict__ Bt,
                   const float* __restrict__ bias, CT* __restrict__ C,
                   int N, int K)
{
    __shared__ __align__(16) char sS[GSTAGES][16384];  // per stage: A[0,8K), B[8K,16K)

    const int tid  = threadIdx.x;
    const int lane = tid & 31;
    const int warp = tid >> 5;
    const int g    = lane >> 2;
    const int tig  = lane & 3;
    const int bm   = blockIdx.y * 128;
    const int bn   = blockIdx.x * 128;
    const int m0   = (warp >> 1) * 64;
    const int n0   = (warp & 1) * 64;

    // loader: thread -> rows lr+32j (j=0..3), 16B chunk lc; key invariant in j
    const int lr = tid >> 2;          // 0..31
    const int lc = tid & 3;
    const uint32_t sco = (uint32_t)(((lc ^ ((lr >> 1) & 3))) << 4);
    uint32_t soff[4];
    #pragma unroll
    for (int j = 0; j < 4; j++) soff[j] = (uint32_t)((lr + 32 * j) * 64) + sco;
    const __half* Ag = A  + (size_t)(bm + lr) * K + lc * 8;
    const __half* Bg = Bt + (size_t)(bn + lr) * K + lc * 8;
    const int rowStrideA = 32 * K;

    const uint32_t sBase = smem_u32(sS);

    // fragment ldmatrix addresses (byte offsets within a stage)
    const int r8 = lane & 7;
    uint32_t aoff[4], boff[4];
    #pragma unroll
    for (int mt = 0; mt < 4; mt++) {
        const int m = m0 + mt * 16 + r8 + ((lane >> 3) & 1) * 8;
        const int c = lane >> 4;
        aoff[mt] = (uint32_t)(m * 64 + ((c ^ ((m >> 1) & 3)) << 4));
    }
    #pragma unroll
    for (int nb = 0; nb < 4; nb++) {
        const int n = n0 + nb * 16 + r8 + (lane >> 4) * 8;
        const int c = (lane >> 3) & 1;
        boff[nb] = (uint32_t)(8192 + n * 64 + ((c ^ ((n >> 1) & 3)) << 4));
    }

    float acc[4][8][4];
    #pragma unroll
    for (int a = 0; a < 4; a++)
        #pragma unroll
        for (int b = 0; b < 8; b++)
            #pragma unroll
            for (int c = 0; c < 4; c++) acc[a][b][c] = 0.f;

    const int T = K >> 5;   // BK = 32

    // prologue: prefetch tiles 0..GSTAGES-2
    #pragma unroll
    for (int p = 0; p < GSTAGES - 1; p++) {
        const uint32_t sb = sBase + p * 16384;
        const __half* a = Ag + p * 32;
        const __half* b = Bg + p * 32;
        #pragma unroll
        for (int j = 0; j < 4; j++) {
            cp_async16(sb + soff[j],        a + j * rowStrideA);
            cp_async16(sb + 8192 + soff[j], b + j * rowStrideA);
        }
        cp_commit();
    }

    for (int t = 0; t < T; t++) {
        cp_wait<GSTAGES - 2>();
        __syncthreads();

        // prefetch tile t+GSTAGES-1 into the stage just freed (tile t-1's)
        if (t + GSTAGES - 1 < T) {
            const int st = (t + GSTAGES - 1) % GSTAGES;
            const uint32_t sb = sBase + st * 16384;
            const __half* a = Ag + (t + GSTAGES - 1) * 32;
            const __half* b = Bg + (t + GSTAGES - 1) * 32;
            #pragma unroll
            for (int j = 0; j < 4; j++) {
                cp_async16(sb + soff[j],        a + j * rowStrideA);
                cp_async16(sb + 8192 + soff[j], b + j * rowStrideA);
            }
        }
        cp_commit();

        const uint32_t sb = sBase + (t % GSTAGES) * 16384;
        #pragma unroll
        for (int s = 0; s < 2; s++) {
            const uint32_t sx = (uint32_t)(s << 5);   // chunk +2 == XOR 32 bytes
            uint32_t afr[4][4], bfr[4][4];
            #pragma unroll
            for (int mt = 0; mt < 4; mt++)
                ldsm_x4(afr[mt], sb + (aoff[mt] ^ sx));
            #pragma unroll
            for (int nb = 0; nb < 4; nb++)
                ldsm_x4(bfr[nb], sb + (boff[nb] ^ sx));
            #pragma unroll
            for (int mt = 0; mt < 4; mt++)
                #pragma unroll
                for (int nb = 0; nb < 4; nb++) {
                    mma_f16(acc[mt][nb * 2],     afr[mt], &bfr[nb][0]);
                    mma_f16(acc[mt][nb * 2 + 1], afr[mt], &bfr[nb][2]);
                }
        }
    }

    // Epilogue: bias + store
    #pragma unroll
    for (int mt = 0; mt < 4; mt++) {
        #pragma unroll
        for (int nt = 0; nt < 8; nt++) {
            const int row0 = bm + m0 + mt * 16 + g;
            const int col0 = bn + n0 + nt * 8 + tig * 2;
            const float b0 = __ldg(bias + col0);
            const float b1 = __ldg(bias + col0 + 1);
            if constexpr (sizeof(CT) == 2) {
                *(uint32_t*)((__half*)C + (size_t)row0 * N + col0) =
                    pack_h2(acc[mt][nt][0] + b0, acc[mt][nt][1] + b1);
                *(uint32_t*)((__half*)C + (size_t)(row0 + 8) * N + col0) =
                    pack_h2(acc[mt][nt][2] + b0, acc[mt][nt][3] + b1);
            } else {
                float2 r0, r1;
                r0.x = acc[mt][nt][0] + b0; r0.y = acc[mt][nt][1] + b1;
                r1.x = acc[mt][nt][2] + b0; r1.y = acc[mt][nt][3] + b1;
                *(float2*)((float*)C + (size_t)row0 * N + col0)       = r0;
                *(float2*)((float*)C + (size_t)(row0 + 8) * N + col0) = r1;
            }
        }
    }
}

// ---------------------------------------------------------------------------
// Windowed attention, full fp16 mma.sync (unchanged from R14).
// Block = (head, window), 128 threads = 4 warps, warp w owns query rows
// [16w, 16w+16). S = Q*K^T (k16 x2), softmax in accumulator layout (scale
// folded into bias FFMA), P packed to fp16 smem, O = P*V with V consumed in
// natural (key-major) layout via ldmatrix.trans.
//   pixel(h) = (wh*8 + ph + 4) & 63   (same for w)
// ---------------------------------------------------------------------------
__device__ __forceinline__ int pix_row(int win, int t) {
    const int b  = win >> 6;
    const int wi = win & 63;
    const int h  = (((wi >> 3) << 3) + (t >> 3) + 4) & 63;
    const int w  = (((wi & 7) << 3) + (t & 7) + 4) & 63;
    return (((b << 6) | h) << 6) | w;   // b*4096 + h*64 + w
}

__global__ __launch_bounds__(128)
void attn_h_kernel(const __half* __restrict__ qkv, const float* __restrict__ rel_pos,
                   __half* __restrict__ att)
{
    const int head = blockIdx.x;
    const int win  = blockIdx.y;
    const int tid  = threadIdx.x;
    const int lane = tid & 31;
    const int g    = lane >> 2;
    const int tig  = lane & 3;
    const int m0   = (tid >> 5) * 16;

    __shared__ __align__(16) char sQ[4096];
    __shared__ __align__(16) char sK[4096];
    __shared__ __align__(16) char sV[4096];
    __shared__ __align__(16) char sP[8192];
    __shared__ float rp[225];

    const uint32_t qB = smem_u32(sQ);
    const uint32_t kB = smem_u32(sK);
    const uint32_t vB = smem_u32(sV);
    const uint32_t pB = smem_u32(sP);

    for (int i = tid; i < 225; i += 128) rp[i] = __ldg(rel_pos + i * NHEADS + head);
    {
        const int row  = tid >> 1;
        const int half = tid & 1;
        const size_t base = (size_t)pix_row(win, row) * N_QKV + head * 32;
        const uint4* qp = (const uint4*)(qkv + base);
        const uint4* kp = (const uint4*)(qkv + base + 512);
        const uint4* vp = (const uint4*)(qkv + base + 1024);
        const int key = (row >> 1) & 3;
        #pragma unroll
        for (int u = 0; u < 2; u++) {
            const int c = half * 2 + u;
            const uint32_t sw = (uint32_t)(row * 64 + ((c ^ key) << 4));
            *(uint4*)(sQ + sw) = __ldg(qp + c);
            *(uint4*)(sK + sw) = __ldg(kp + c);
            *(uint4*)(sV + sw) = __ldg(vp + c);
        }
    }
    __syncthreads();

    const int r8 = lane & 7;
    uint32_t aoffQ, boffK[4];
    {
        const int m = m0 + r8 + ((lane >> 3) & 1) * 8;
        const int c = lane >> 4;
        aoffQ = (uint32_t)(m * 64 + ((c ^ ((m >> 1) & 3)) << 4));
    }
    #pragma unroll
    for (int nb = 0; nb < 4; nb++) {
        const int n = nb * 16 + r8 + (lane >> 4) * 8;
        const int c = (lane >> 3) & 1;
        boffK[nb] = (uint32_t)(n * 64 + ((c ^ ((n >> 1) & 3)) << 4));
    }

    float acc[8][4];
    #pragma unroll
    for (int nt = 0; nt < 8; nt++)
        #pragma unroll
        for (int c = 0; c < 4; c++) acc[nt][c] = 0.f;

    #pragma unroll
    for (int kt = 0; kt < 2; kt++) {
        const uint32_t sx = (uint32_t)(kt << 5);
        uint32_t a[4];
        ldsm_x4(a, qB + (aoffQ ^ sx));
        #pragma unroll
        for (int nb = 0; nb < 4; nb++) {
            uint32_t b[4];
            ldsm_x4(b, kB + (boffK[nb] ^ sx));
            mma_f16(acc[nb * 2],     a, b);
            mma_f16(acc[nb * 2 + 1], a, b + 2);
        }
    }

    const float scale = 0.17677669529663687f;   // 1/sqrt(32)
    const int i0 = m0 + g;
    const int yi = i0 >> 3, xi = i0 & 7;
    float mx0 = -1e30f, mx1 = -1e30f;
    #pragma unroll
    for (int nt = 0; nt < 8; nt++) {
        const int bi = (yi - nt + 7) * 15 + (xi - 2 * tig + 7);
        acc[nt][0] = fmaf(acc[nt][0], scale, rp[bi]);
        acc[nt][1] = fmaf(acc[nt][1], scale, rp[bi - 1]);
        acc[nt][2] = fmaf(acc[nt][2], scale, rp[bi + 15]);
        acc[nt][3] = fmaf(acc[nt][3], scale, rp[bi + 14]);
        mx0 = fmaxf(mx0, fmaxf(acc[nt][0], acc[nt][1]));
        mx1 = fmaxf(mx1, fmaxf(acc[nt][2], acc[nt][3]));
    }
    mx0 = fmaxf(mx0, __shfl_xor_sync(0xffffffffu, mx0, 1));
    mx0 = fmaxf(mx0, __shfl_xor_sync(0xffffffffu, mx0, 2));
    mx1 = fmaxf(mx1, __shfl_xor_sync(0xffffffffu, mx1, 1));
    mx1 = fmaxf(mx1, __shfl_xor_sync(0xffffffffu, mx1, 2));

    float s0 = 0.f, s1 = 0.f;
    #pragma unroll
    for (int nt = 0; nt < 8; nt++) {
        acc[nt][0] = __expf(acc[nt][0] - mx0);
        acc[nt][1] = __expf(acc[nt][1] - mx0);
        acc[nt][2] = __expf(acc[nt][2] - mx1);
        acc[nt][3] = __expf(acc[nt][3] - mx1);
        s0 += acc[nt][0] + acc[nt][1];
        s1 += acc[nt][2] + acc[nt][3];
    }
    s0 += __shfl_xor_sync(0xffffffffu, s0, 1);
    s0 += __shfl_xor_sync(0xffffffffu, s0, 2);
    s1 += __shfl_xor_sync(0xffffffffu, s1, 1);
    s1 += __shfl_xor_sync(0xffffffffu, s1, 2);
    const float inv0 = 1.0f / s0;
    const float inv1 = 1.0f / s1;

    {
        const int keyP = i0 & 7;
        #pragma unroll
        for (int nt = 0; nt < 8; nt++) {
            const uint32_t a0 = (uint32_t)(i0 * 128       + ((nt ^ keyP) << 4) + 4 * tig);
            const uint32_t a1 = (uint32_t)((i0 + 8) * 128 + ((nt ^ keyP) << 4) + 4 * tig);
            *(uint32_t*)(sP + a0) = pack_h2(acc[nt][0] * inv0, acc[nt][1] * inv0);
            *(uint32_t*)(sP + a1) = pack_h2(acc[nt][2] * inv1, acc[nt][3] * inv1);
        }
    }
    __syncwarp();

    float accO[4][4];
    #pragma unroll
    for (int nt = 0; nt < 4; nt++)
        #pragma unroll
        for (int c = 0; c < 4; c++) accO[nt][c] = 0.f;

    uint32_t aoffP;
    {
        const int m = m0 + r8 + ((lane >> 3) & 1) * 8;
        const int c = lane >> 4;
        aoffP = (uint32_t)(m * 128 + ((c ^ (m & 7)) << 4));
    }
    uint32_t voff[2];
    {
        const int rb  = r8 + ((lane >> 3) & 1) * 8;
        const int key = (rb >> 1) & 3;
        #pragma unroll
        for (int nb = 0; nb < 2; nb++) {
            const int c = nb * 2 + (lane >> 4);
            voff[nb] = (uint32_t)(rb * 64 + ((c ^ key) << 4));
        }
    }

    #pragma unroll
    for (int kt = 0; kt < 4; kt++) {
        uint32_t a[4];
        ldsm_x4(a, pB + (aoffP ^ ((uint32_t)kt << 5)));
        #pragma unroll
        for (int nb = 0; nb < 2; nb++) {
            uint32_t b[4];
            ldsm_x4_t(b, vB + voff[nb] + (uint32_t)kt * 1024);
            mma_f16(accO[nb * 2],     a, b);
            mma_f16(accO[nb * 2 + 1], a, b + 2);
        }
    }

    {
        const size_t r0 = (size_t)pix_row(win, i0)     * N_OUT + head * 32;
        const size_t r1 = (size_t)pix_row(win, i0 + 8) * N_OUT + head * 32;
        #pragma unroll
        for (int nt = 0; nt < 4; nt++) {
            *(uint32_t*)(att + r0 + nt * 8 + 2 * tig) = pack_h2(accO[nt][0], accO[nt][1]);
            *(uint32_t*)(att + r1 + nt * 8 + 2 * tig) = pack_h2(accO[nt][2], accO[nt][3]);
        }
    }
}

// ---------------------------------------------------------------------------
extern "C" void kernel_launch(void* const* d_in, const int* in_sizes, int n_in,
                              void* d_out, int out_size)
{
    const float* x       = (const float*)d_in[0];
    const float* w_qkv   = (const float*)d_in[1];
    const float* b_qkv   = (const float*)d_in[2];
    const float* rel_pos = (const float*)d_in[3];
    const float* w_out   = (const float*)d_in[4];
    const float* b_out   = (const float*)d_in[5];
    float* out = (float*)d_out;

    __half *xh, *qkvh, *atth, *btqh, *btoh;
    cudaGetSymbolAddress((void**)&xh,   g_xh);
    cudaGetSymbolAddress((void**)&qkvh, g_qkvh);
    cudaGetSymbolAddress((void**)&atth, g_atth);
    cudaGetSymbolAddress((void**)&btqh, g_btqh);
    cudaGetSymbolAddress((void**)&btoh, g_btoh);

    // 0) convert inputs to fp16 once per launch
    {
        const size_t n8 = (size_t)M_TOK * KDIM / 8;
        f2h_kernel<<<(unsigned)((n8 + 255) / 256), 256>>>(x, xh, n8);
    }
    transpose_h_kernel<<<dim3(N_QKV / 32, KDIM / 32), dim3(32, 8)>>>(w_qkv, btqh, KDIM, N_QKV);
    transpose_h_kernel<<<dim3(N_OUT / 32, KDIM / 32), dim3(32, 8)>>>(w_out, btoh, KDIM, N_OUT);

    // 1) QKV projection (fp16 in/out)
    gemm_h_kernel<__half><<<dim3(N_QKV / 128, M_TOK / 128), 128>>>(
        xh, btqh, b_qkv, qkvh, N_QKV, KDIM);

    // 2) Shifted-window attention (fp16 in/out)
    attn_h_kernel<<<dim3(NHEADS, 1024), dim3(128)>>>(qkvh, rel_pos, atth);

    // 3) Output projection (fp16 in, fp32 out)
    gemm_h_kernel<float><<<dim3(N_OUT / 128, M_TOK / 128), 128>>>(
        atth, btoh, b_out, out, N_OUT, KDIM);
}